// round 1
// baseline (speedup 1.0000x reference)
#include <cuda_runtime.h>

#define NN 50000
#define NE 800000
#define NG 1024
#define NFEAT 32
#define NREL 4
#define NH 64
#define NO 16
#define MAXDEG 10

// ---------------- scratch (device globals; no allocations allowed) ----------------
__device__ float g_h[NN * NH];        // node features (block input/output buffer)
__device__ float g_hmid[NN * NH];     // RGCN output (pre-relu)
__device__ float g_aggm[NN * NH];     // MFConv neighbor sums
__device__ float g_hx[5 * NN * NH];   // per-relation transformed features + root (64 MB)
__device__ float g_pool[NG * NH];     // pooled graph features
__device__ float g_invw[NN * NREL];   // 1/cnt per (node, rel)
__device__ int   g_cnt[NN * NREL];
__device__ int   g_indeg[NN];
__device__ int   g_off[NN + 1];
__device__ int   g_cur[NN];
__device__ int   g_csr[NE];           // (rel<<28) | src, grouped by target
__device__ int   g_rel[NE];
__device__ int   g_deg[NN];
__device__ int   g_bcnt[MAXDEG + 1];
__device__ int   g_boff[MAXDEG + 1];
__device__ int   g_bcur[MAXDEG + 1];
__device__ int   g_bnodes[NN];

// ---------------- zero scratch counters ----------------
__global__ void zero_kernel() {
    int i = blockIdx.x * 256 + threadIdx.x;
    if (i < NN * NREL) g_cnt[i] = 0;
    if (i < NN) { g_indeg[i] = 0; g_cur[i] = 0; }
    if (i < NG * NH) g_pool[i] = 0.f;
    if (i <= MAXDEG) { g_bcnt[i] = 0; g_bcur[i] = 0; }
}

// ---------------- node init: argmax(x) -> emb lookup ----------------
__global__ void node_init_kernel(const float* __restrict__ x, const float* __restrict__ emb) {
    int n = blockIdx.x * 128 + threadIdx.x;
    if (n >= NN) return;
    const float4* xr = (const float4*)(x + (size_t)n * NFEAT);
    float best = -1e30f; int bi = 0;
#pragma unroll
    for (int q = 0; q < NFEAT / 4; q++) {
        float4 v = xr[q];
        if (v.x > best) { best = v.x; bi = q * 4 + 0; }
        if (v.y > best) { best = v.y; bi = q * 4 + 1; }
        if (v.z > best) { best = v.z; bi = q * 4 + 2; }
        if (v.w > best) { best = v.w; bi = q * 4 + 3; }
    }
    const float4* er = (const float4*)(emb + bi * NH);
    float4* hr = (float4*)(g_h + (size_t)n * NH);
#pragma unroll
    for (int q = 0; q < NH / 4; q++) hr[q] = er[q];
}

// ---------------- edge prep: rel argmax + counts ----------------
__global__ void edge_prep_kernel(const float* __restrict__ ea, const int* __restrict__ ei) {
    int e = blockIdx.x * 256 + threadIdx.x;
    if (e >= NE) return;
    float4 a = ((const float4*)ea)[e];
    int rel = 0; float best = a.x;
    if (a.y > best) { best = a.y; rel = 1; }
    if (a.z > best) { best = a.z; rel = 2; }
    if (a.w > best) { best = a.w; rel = 3; }
    g_rel[e] = rel;
    int t = ei[NE + e];
    atomicAdd(&g_cnt[t * NREL + rel], 1);
    atomicAdd(&g_indeg[t], 1);
}

// ---------------- single-block exclusive scan of indeg -> offsets ----------------
__global__ void scan_kernel() {
    __shared__ int wpre[32];
    __shared__ int s_run, s_chunk;
    int tid = threadIdx.x, lane = tid & 31, warp = tid >> 5;
    if (tid == 0) s_run = 0;
    __syncthreads();
    for (int base = 0; base < NN; base += 1024) {
        int i = base + tid;
        int v = (i < NN) ? g_indeg[i] : 0;
        int incl = v;
#pragma unroll
        for (int o = 1; o < 32; o <<= 1) {
            int t = __shfl_up_sync(0xffffffffu, incl, o);
            if (lane >= o) incl += t;
        }
        if (lane == 31) wpre[warp] = incl;
        __syncthreads();
        if (warp == 0) {
            int wv = wpre[lane];
            int wi = wv;
#pragma unroll
            for (int o = 1; o < 32; o <<= 1) {
                int t = __shfl_up_sync(0xffffffffu, wi, o);
                if (lane >= o) wi += t;
            }
            wpre[lane] = wi - wv;
            if (lane == 31) s_chunk = wi;
        }
        __syncthreads();
        if (i < NN) g_off[i] = s_run + wpre[warp] + incl - v;
        __syncthreads();
        if (tid == 0) s_run += s_chunk;
        __syncthreads();
    }
    if (threadIdx.x == 0) g_off[NN] = s_run;
}

// ---------------- inv weights + degree buckets ----------------
__global__ void invdeg_kernel() {
    int n = blockIdx.x * 256 + threadIdx.x;
    if (n >= NN) return;
#pragma unroll
    for (int r = 0; r < NREL; r++) {
        int c = g_cnt[n * NREL + r];
        g_invw[n * NREL + r] = c ? (1.0f / (float)c) : 0.f;
    }
    int d = min(g_indeg[n], MAXDEG);
    g_deg[n] = d;
    atomicAdd(&g_bcnt[d], 1);
}

__global__ void bucket_scan_kernel() {
    if (threadIdx.x == 0) {
        int run = 0;
        for (int d = 0; d <= MAXDEG; d++) { g_boff[d] = run; run += g_bcnt[d]; }
    }
}

__global__ void csr_fill_kernel(const int* __restrict__ ei) {
    int e = blockIdx.x * 256 + threadIdx.x;
    if (e >= NE) return;
    int t = ei[NE + e];
    int pos = g_off[t] + atomicAdd(&g_cur[t], 1);
    g_csr[pos] = (g_rel[e] << 28) | ei[e];
}

__global__ void bucket_fill_kernel() {
    int n = blockIdx.x * 256 + threadIdx.x;
    if (n >= NN) return;
    int d = g_deg[n];
    int pos = g_boff[d] + atomicAdd(&g_bcur[d], 1);
    g_bnodes[pos] = n;
}

// ---------------- hx[m] = relu(h) @ Wm  (m=0..3 relations, m=4 root) ----------------
__global__ __launch_bounds__(128) void gemm_hx_kernel(const float* __restrict__ W,
                                                      const float* __restrict__ Wroot) {
    __shared__ float AsT[NH][128];        // 32 KB (A transposed, relu applied)
    __shared__ float Bs[NH * NH];         // 16 KB
    const float* __restrict__ B = (blockIdx.y < 4) ? (W + blockIdx.y * NH * NH) : Wroot;
    int tid = threadIdx.x;

    const float4* B4 = (const float4*)B;
    float4* Bs4 = (float4*)Bs;
#pragma unroll
    for (int i = 0; i < 8; i++) Bs4[i * 128 + tid] = B4[i * 128 + tid];

    int row = blockIdx.x * 128 + tid;
    if (row < NN) {
        const float4* ar = (const float4*)(g_h + (size_t)row * NH);
#pragma unroll
        for (int c4 = 0; c4 < 16; c4++) {
            float4 v = ar[c4];
            AsT[c4 * 4 + 0][tid] = fmaxf(v.x, 0.f);
            AsT[c4 * 4 + 1][tid] = fmaxf(v.y, 0.f);
            AsT[c4 * 4 + 2][tid] = fmaxf(v.z, 0.f);
            AsT[c4 * 4 + 3][tid] = fmaxf(v.w, 0.f);
        }
    } else {
#pragma unroll
        for (int c = 0; c < NH; c++) AsT[c][tid] = 0.f;
    }
    __syncthreads();

    int ty = tid >> 3, tx = tid & 7;       // 16 row groups x 8 col groups, 8x8 micro
    float acc[8][8];
#pragma unroll
    for (int i = 0; i < 8; i++)
#pragma unroll
        for (int j = 0; j < 8; j++) acc[i][j] = 0.f;

#pragma unroll 4
    for (int k = 0; k < NH; k++) {
        float4 a0 = *(const float4*)&AsT[k][ty * 8];
        float4 a1 = *(const float4*)&AsT[k][ty * 8 + 4];
        float4 b0 = *(const float4*)&Bs[k * NH + tx * 8];
        float4 b1 = *(const float4*)&Bs[k * NH + tx * 8 + 4];
        float av[8] = {a0.x, a0.y, a0.z, a0.w, a1.x, a1.y, a1.z, a1.w};
        float bv[8] = {b0.x, b0.y, b0.z, b0.w, b1.x, b1.y, b1.z, b1.w};
#pragma unroll
        for (int i = 0; i < 8; i++)
#pragma unroll
            for (int j = 0; j < 8; j++) acc[i][j] += av[i] * bv[j];
    }

    float* C = g_hx + (size_t)blockIdx.y * (NN * NH);
    int rbase = blockIdx.x * 128 + ty * 8;
#pragma unroll
    for (int i = 0; i < 8; i++) {
        int r = rbase + i;
        if (r < NN) {
            float4* o = (float4*)(C + (size_t)r * NH + tx * 8);
            o[0] = make_float4(acc[i][0], acc[i][1], acc[i][2], acc[i][3]);
            o[1] = make_float4(acc[i][4], acc[i][5], acc[i][6], acc[i][7]);
        }
    }
}

// ---------------- RGCN pull aggregation: hmid[t] = sum_e inv*hx[rel][src] + hx[4][t] + b ----------------
__global__ __launch_bounds__(256) void rgcn_agg_kernel(const float* __restrict__ bias) {
    int tid = threadIdx.x;
    int node = blockIdx.x * 4 + (tid >> 6);
    if (node >= NN) return;
    int dim = tid & 63;
    int beg = g_off[node], end = g_off[node + 1];
    float acc = g_hx[4 * NN * NH + node * NH + dim] + bias[dim];
    float iw0 = g_invw[node * NREL + 0];
    float iw1 = g_invw[node * NREL + 1];
    float iw2 = g_invw[node * NREL + 2];
    float iw3 = g_invw[node * NREL + 3];
    int i = beg;
    for (; i + 4 <= end; i += 4) {
        int p0 = g_csr[i], p1 = g_csr[i + 1], p2 = g_csr[i + 2], p3 = g_csr[i + 3];
        float v0 = g_hx[((p0 >> 28) * NN + (p0 & 0x0FFFFFFF)) * NH + dim];
        float v1 = g_hx[((p1 >> 28) * NN + (p1 & 0x0FFFFFFF)) * NH + dim];
        float v2 = g_hx[((p2 >> 28) * NN + (p2 & 0x0FFFFFFF)) * NH + dim];
        float v3 = g_hx[((p3 >> 28) * NN + (p3 & 0x0FFFFFFF)) * NH + dim];
        float w0 = (p0 >> 28) == 0 ? iw0 : (p0 >> 28) == 1 ? iw1 : (p0 >> 28) == 2 ? iw2 : iw3;
        float w1 = (p1 >> 28) == 0 ? iw0 : (p1 >> 28) == 1 ? iw1 : (p1 >> 28) == 2 ? iw2 : iw3;
        float w2 = (p2 >> 28) == 0 ? iw0 : (p2 >> 28) == 1 ? iw1 : (p2 >> 28) == 2 ? iw2 : iw3;
        float w3 = (p3 >> 28) == 0 ? iw0 : (p3 >> 28) == 1 ? iw1 : (p3 >> 28) == 2 ? iw2 : iw3;
        acc += v0 * w0 + v1 * w1 + v2 * w2 + v3 * w3;
    }
    for (; i < end; i++) {
        int p = g_csr[i];
        int rel = p >> 28;
        float w = (rel == 0) ? iw0 : (rel == 1) ? iw1 : (rel == 2) ? iw2 : iw3;
        acc += g_hx[(rel * NN + (p & 0x0FFFFFFF)) * NH + dim] * w;
    }
    g_hmid[node * NH + dim] = acc;
}

// ---------------- MFConv pull aggregation: aggm[t] = sum relu(hmid[src]) ----------------
__global__ __launch_bounds__(256) void mf_agg_kernel() {
    int tid = threadIdx.x;
    int node = blockIdx.x * 4 + (tid >> 6);
    if (node >= NN) return;
    int dim = tid & 63;
    int beg = g_off[node], end = g_off[node + 1];
    float acc = 0.f;
    int i = beg;
    for (; i + 4 <= end; i += 4) {
        int s0 = g_csr[i] & 0x0FFFFFFF, s1 = g_csr[i + 1] & 0x0FFFFFFF;
        int s2 = g_csr[i + 2] & 0x0FFFFFFF, s3 = g_csr[i + 3] & 0x0FFFFFFF;
        acc += fmaxf(g_hmid[s0 * NH + dim], 0.f) + fmaxf(g_hmid[s1 * NH + dim], 0.f)
             + fmaxf(g_hmid[s2 * NH + dim], 0.f) + fmaxf(g_hmid[s3 * NH + dim], 0.f);
    }
    for (; i < end; i++)
        acc += fmaxf(g_hmid[(g_csr[i] & 0x0FFFFFFF) * NH + dim], 0.f);
    g_aggm[node * NH + dim] = acc;
}

// ---------------- MFConv degree-bucketed GEMM: h[n] = aggm@Wl[d] + bl[d] + relu(hmid)@Wr[d] ----------------
__global__ __launch_bounds__(128) void mf_gemm_kernel(const float* __restrict__ Wl,
                                                      const float* __restrict__ bl,
                                                      const float* __restrict__ Wr) {
    __shared__ float AsT[NH][64];      // 16 KB
    __shared__ float Bs[NH * NH];      // 16 KB
    __shared__ int nodes[64];
    int d = blockIdx.y;
    int cnt = g_bcnt[d];
    int t0 = blockIdx.x * 64;
    if (t0 >= cnt) return;
    int tid = threadIdx.x;
    if (tid < 64) {
        int idx = t0 + tid;
        nodes[tid] = (idx < cnt) ? g_bnodes[g_boff[d] + idx] : -1;
    }
    const float4* B4 = (const float4*)(Wl + d * NH * NH);
    float4* Bs4 = (float4*)Bs;
#pragma unroll
    for (int i = 0; i < 8; i++) Bs4[i * 128 + tid] = B4[i * 128 + tid];
    __syncthreads();

    int r = tid & 63, half = tid >> 6;
    {
        int n = nodes[r];
        if (n >= 0) {
            const float4* ar = (const float4*)(g_aggm + (size_t)n * NH);
#pragma unroll
            for (int c4 = 0; c4 < 8; c4++) {
                int c = half * 8 + c4;
                float4 v = ar[c];
                AsT[c * 4 + 0][r] = v.x; AsT[c * 4 + 1][r] = v.y;
                AsT[c * 4 + 2][r] = v.z; AsT[c * 4 + 3][r] = v.w;
            }
        } else {
#pragma unroll
            for (int c4 = 0; c4 < 8; c4++) {
                int c = half * 8 + c4;
                AsT[c * 4 + 0][r] = 0.f; AsT[c * 4 + 1][r] = 0.f;
                AsT[c * 4 + 2][r] = 0.f; AsT[c * 4 + 3][r] = 0.f;
            }
        }
    }
    __syncthreads();

    int ty = tid >> 3, tx = tid & 7;   // rows ty*4..+3, cols tx*8..+7
    float acc[4][8];
#pragma unroll
    for (int i = 0; i < 4; i++)
#pragma unroll
        for (int j = 0; j < 8; j++) acc[i][j] = 0.f;

#pragma unroll 4
    for (int k = 0; k < NH; k++) {
        float4 a = *(const float4*)&AsT[k][ty * 4];
        float4 b0 = *(const float4*)&Bs[k * NH + tx * 8];
        float4 b1 = *(const float4*)&Bs[k * NH + tx * 8 + 4];
        float av[4] = {a.x, a.y, a.z, a.w};
        float bv[8] = {b0.x, b0.y, b0.z, b0.w, b1.x, b1.y, b1.z, b1.w};
#pragma unroll
        for (int i = 0; i < 4; i++)
#pragma unroll
            for (int j = 0; j < 8; j++) acc[i][j] += av[i] * bv[j];
    }
    __syncthreads();

    // phase 2: Wr with relu(hmid)
    B4 = (const float4*)(Wr + d * NH * NH);
#pragma unroll
    for (int i = 0; i < 8; i++) Bs4[i * 128 + tid] = B4[i * 128 + tid];
    {
        int n = nodes[r];
        if (n >= 0) {
            const float4* ar = (const float4*)(g_hmid + (size_t)n * NH);
#pragma unroll
            for (int c4 = 0; c4 < 8; c4++) {
                int c = half * 8 + c4;
                float4 v = ar[c];
                AsT[c * 4 + 0][r] = fmaxf(v.x, 0.f); AsT[c * 4 + 1][r] = fmaxf(v.y, 0.f);
                AsT[c * 4 + 2][r] = fmaxf(v.z, 0.f); AsT[c * 4 + 3][r] = fmaxf(v.w, 0.f);
            }
        } else {
#pragma unroll
            for (int c4 = 0; c4 < 8; c4++) {
                int c = half * 8 + c4;
                AsT[c * 4 + 0][r] = 0.f; AsT[c * 4 + 1][r] = 0.f;
                AsT[c * 4 + 2][r] = 0.f; AsT[c * 4 + 3][r] = 0.f;
            }
        }
    }
    __syncthreads();

#pragma unroll 4
    for (int k = 0; k < NH; k++) {
        float4 a = *(const float4*)&AsT[k][ty * 4];
        float4 b0 = *(const float4*)&Bs[k * NH + tx * 8];
        float4 b1 = *(const float4*)&Bs[k * NH + tx * 8 + 4];
        float av[4] = {a.x, a.y, a.z, a.w};
        float bv[8] = {b0.x, b0.y, b0.z, b0.w, b1.x, b1.y, b1.z, b1.w};
#pragma unroll
        for (int i = 0; i < 4; i++)
#pragma unroll
            for (int j = 0; j < 8; j++) acc[i][j] += av[i] * bv[j];
    }

#pragma unroll
    for (int i = 0; i < 4; i++) {
        int rr = ty * 4 + i;
        int n = nodes[rr];
        if (n >= 0) {
            float* o = g_h + (size_t)n * NH + tx * 8;
            const float* bb = bl + d * NH + tx * 8;
            float4 o0 = make_float4(acc[i][0] + bb[0], acc[i][1] + bb[1],
                                    acc[i][2] + bb[2], acc[i][3] + bb[3]);
            float4 o1 = make_float4(acc[i][4] + bb[4], acc[i][5] + bb[5],
                                    acc[i][6] + bb[6], acc[i][7] + bb[7]);
            ((float4*)o)[0] = o0;
            ((float4*)o)[1] = o1;
        }
    }
}

// ---------------- global add pool ----------------
__global__ void pool_kernel(const int* __restrict__ batch) {
    int i = blockIdx.x * 256 + threadIdx.x;
    if (i >= NN * NH) return;
    int n = i >> 6;
    atomicAdd(&g_pool[batch[n] * NH + (i & 63)], g_h[i]);
}

// ---------------- head MLP: relu(g@l1+b1)@l2+b2 ----------------
__global__ __launch_bounds__(256) void mlp_kernel(const float* __restrict__ l1w, const float* __restrict__ l1b,
                                                  const float* __restrict__ l2w, const float* __restrict__ l2b,
                                                  float* __restrict__ out) {
    __shared__ float s1[NH * NH];
    __shared__ float s2[NH * NO];
    __shared__ float sg[8][NH];
    int tid = threadIdx.x, lane = tid & 31, w = tid >> 5;
#pragma unroll
    for (int i = 0; i < 16; i++) s1[i * 256 + tid] = l1w[i * 256 + tid];
#pragma unroll
    for (int i = 0; i < 4; i++) s2[i * 256 + tid] = l2w[i * 256 + tid];
    int gidx = blockIdx.x * 8 + w;
    sg[w][lane] = g_pool[gidx * NH + lane];
    sg[w][lane + 32] = g_pool[gidx * NH + lane + 32];
    __syncthreads();
    float t0 = l1b[lane], t1 = l1b[lane + 32];
#pragma unroll 8
    for (int k = 0; k < NH; k++) {
        float gv = sg[w][k];
        t0 += gv * s1[k * NH + lane];
        t1 += gv * s1[k * NH + lane + 32];
    }
    t0 = fmaxf(t0, 0.f); t1 = fmaxf(t1, 0.f);
    __syncwarp();
    sg[w][lane] = t0; sg[w][lane + 32] = t1;
    __syncwarp();
    if (lane < NO) {
        float acc = l2b[lane];
#pragma unroll 8
        for (int j = 0; j < NH; j++) acc += sg[w][j] * s2[j * NO + lane];
        out[gidx * NO + lane] = acc;
    }
}

// ---------------- launch ----------------
extern "C" void kernel_launch(void* const* d_in, const int* in_sizes, int n_in,
                              void* d_out, int out_size) {
    const float *x, *ea, *emb, *l1w, *l1b, *l2w, *l2b;
    const int *ei, *batch;
    const float *rw[2], *rro[2], *rb[2], *wl[2], *bll[2], *wr[2];

    if (in_sizes[1] == NE * NREL) {
        // setup_inputs dict order:
        // x, edge_attr, edge_index, batch_idx, emb, lin1_w, lin1_b, lin2_w, lin2_b,
        // then per block: rgcn_w, rgcn_root, rgcn_b, mf_wl, mf_bl, mf_wr
        x = (const float*)d_in[0];  ea = (const float*)d_in[1];
        ei = (const int*)d_in[2];   batch = (const int*)d_in[3];
        emb = (const float*)d_in[4];
        l1w = (const float*)d_in[5]; l1b = (const float*)d_in[6];
        l2w = (const float*)d_in[7]; l2b = (const float*)d_in[8];
        for (int b = 0; b < 2; b++) {
            int k = 9 + 6 * b;
            rw[b]  = (const float*)d_in[k + 0];
            rro[b] = (const float*)d_in[k + 1];
            rb[b]  = (const float*)d_in[k + 2];
            wl[b]  = (const float*)d_in[k + 3];
            bll[b] = (const float*)d_in[k + 4];
            wr[b]  = (const float*)d_in[k + 5];
        }
    } else {
        // reference-arg order:
        // x, edge_index, edge_attr, batch_idx, emb, [block0], [block1], lin1_w, lin1_b, lin2_w, lin2_b
        x = (const float*)d_in[0];  ei = (const int*)d_in[1];
        ea = (const float*)d_in[2]; batch = (const int*)d_in[3];
        emb = (const float*)d_in[4];
        for (int b = 0; b < 2; b++) {
            int k = 5 + 6 * b;
            rw[b]  = (const float*)d_in[k + 0];
            rro[b] = (const float*)d_in[k + 1];
            rb[b]  = (const float*)d_in[k + 2];
            wl[b]  = (const float*)d_in[k + 3];
            bll[b] = (const float*)d_in[k + 4];
            wr[b]  = (const float*)d_in[k + 5];
        }
        l1w = (const float*)d_in[17]; l1b = (const float*)d_in[18];
        l2w = (const float*)d_in[19]; l2b = (const float*)d_in[20];
    }
    float* out = (float*)d_out;

    zero_kernel<<<(NN * NREL + 255) / 256, 256>>>();
    node_init_kernel<<<(NN + 127) / 128, 128>>>(x, emb);
    edge_prep_kernel<<<(NE + 255) / 256, 256>>>(ea, ei);
    scan_kernel<<<1, 1024>>>();
    invdeg_kernel<<<(NN + 255) / 256, 256>>>();
    bucket_scan_kernel<<<1, 32>>>();
    csr_fill_kernel<<<(NE + 255) / 256, 256>>>(ei);
    bucket_fill_kernel<<<(NN + 255) / 256, 256>>>();

    for (int b = 0; b < 2; b++) {
        gemm_hx_kernel<<<dim3((NN + 127) / 128, 5), 128>>>(rw[b], rro[b]);
        rgcn_agg_kernel<<<(NN + 3) / 4, 256>>>(rb[b]);
        mf_agg_kernel<<<(NN + 3) / 4, 256>>>();
        mf_gemm_kernel<<<dim3((NN + 63) / 64, MAXDEG + 1), 128>>>(wl[b], bll[b], wr[b]);
    }

    pool_kernel<<<(NN * NH + 255) / 256, 256>>>(batch);
    mlp_kernel<<<NG / 8, 256>>>(l1w, l1b, l2w, l2b, out);
}

// round 2
// speedup vs baseline: 1.1598x; 1.1598x over previous
#include <cuda_runtime.h>

#define NN 50000
#define NE 800000
#define NG 1024
#define NFEAT 32
#define NREL 4
#define NH 64
#define NO 16
#define MAXDEG 10

// ---------------- scratch (device globals) ----------------
__device__ float g_h[NN * NH];          // node features (block input/output)
__device__ float g_hmid[NN * NH];       // RGCN output (pre-relu)
__device__ float g_aggm[NN * NH];       // MFConv neighbor sums
__device__ float g_agg[NN * NREL * NH]; // per-relation aggregated relu(h) (51 MB)
__device__ float g_pool[NG * NH];
__device__ float g_invw[NN * NREL];
__device__ int   g_cnt[NN * NREL];
__device__ int   g_indeg[NN];
__device__ int   g_off[NN];
__device__ int   g_cur[NN];
__device__ int   g_csr[NE];             // (rel<<28) | src, grouped by target
__device__ int   g_rel[NE];
__device__ int   g_deg[NN];
__device__ int   g_bcnt[MAXDEG + 1];
__device__ int   g_boff[MAXDEG + 1];
__device__ int   g_bcur[MAXDEG + 1];
__device__ int   g_bnodes[NN];
__device__ int   g_total;

// ---------------- zero scratch ----------------
__global__ void zero_kernel() {
    int i = blockIdx.x * 256 + threadIdx.x;
    if (i < NN * NREL) g_cnt[i] = 0;
    if (i < NN) g_cur[i] = 0;
    if (i < NG * NH) g_pool[i] = 0.f;
    if (i <= MAXDEG) { g_bcnt[i] = 0; g_bcur[i] = 0; }
    if (i == 0) g_total = 0;
}

// ---------------- node init: argmax(x) -> emb lookup ----------------
__global__ void node_init_kernel(const float* __restrict__ x, const float* __restrict__ emb) {
    int n = blockIdx.x * 128 + threadIdx.x;
    if (n >= NN) return;
    const float4* xr = (const float4*)(x + (size_t)n * NFEAT);
    float best = -1e30f; int bi = 0;
#pragma unroll
    for (int q = 0; q < NFEAT / 4; q++) {
        float4 v = xr[q];
        if (v.x > best) { best = v.x; bi = q * 4 + 0; }
        if (v.y > best) { best = v.y; bi = q * 4 + 1; }
        if (v.z > best) { best = v.z; bi = q * 4 + 2; }
        if (v.w > best) { best = v.w; bi = q * 4 + 3; }
    }
    const float4* er = (const float4*)(emb + bi * NH);
    float4* hr = (float4*)(g_h + (size_t)n * NH);
#pragma unroll
    for (int q = 0; q < NH / 4; q++) hr[q] = er[q];
}

// ---------------- edge prep: rel argmax + per-(tgt,rel) counts ----------------
__global__ void edge_prep_kernel(const float* __restrict__ ea, const int* __restrict__ ei) {
    int e = blockIdx.x * 256 + threadIdx.x;
    if (e >= NE) return;
    float4 a = ((const float4*)ea)[e];
    int rel = 0; float best = a.x;
    if (a.y > best) { best = a.y; rel = 1; }
    if (a.z > best) { best = a.z; rel = 2; }
    if (a.w > best) { best = a.w; rel = 3; }
    g_rel[e] = rel;
    atomicAdd(&g_cnt[ei[NE + e] * NREL + rel], 1);
}

// ---------------- node meta: indeg, inv weights, degree buckets, CSR offsets ----------------
// CSR segments need only be disjoint & contiguous per node, NOT node-ordered ->
// warp-aggregated atomic allocation instead of a global prefix scan.
__global__ void node_meta_kernel() {
    int n = blockIdx.x * 256 + threadIdx.x;
    int lane = threadIdx.x & 31;
    bool valid = n < NN;
    int c0 = 0, c1 = 0, c2 = 0, c3 = 0;
    if (valid) {
        c0 = g_cnt[n * NREL + 0]; c1 = g_cnt[n * NREL + 1];
        c2 = g_cnt[n * NREL + 2]; c3 = g_cnt[n * NREL + 3];
    }
    int ind = c0 + c1 + c2 + c3;
    if (valid) {
        g_invw[n * NREL + 0] = c0 ? 1.0f / (float)c0 : 0.f;
        g_invw[n * NREL + 1] = c1 ? 1.0f / (float)c1 : 0.f;
        g_invw[n * NREL + 2] = c2 ? 1.0f / (float)c2 : 0.f;
        g_invw[n * NREL + 3] = c3 ? 1.0f / (float)c3 : 0.f;
        g_indeg[n] = ind;
    }
    // warp-aggregated offset allocation
    int incl = ind;
#pragma unroll
    for (int o = 1; o < 32; o <<= 1) {
        int t = __shfl_up_sync(0xffffffffu, incl, o);
        if (lane >= o) incl += t;
    }
    int wsum = __shfl_sync(0xffffffffu, incl, 31);
    int base = 0;
    if (lane == 0) base = atomicAdd(&g_total, wsum);
    base = __shfl_sync(0xffffffffu, base, 0);
    if (valid) g_off[n] = base + incl - ind;
    // degree-bucket counts, warp-aggregated
    int d = min(ind, MAXDEG);
    if (valid) g_deg[n] = d;
    unsigned vm = __ballot_sync(0xffffffffu, valid);
    unsigned m = __match_any_sync(0xffffffffu, d) & vm;
    if (valid) {
        int leader = __ffs(m) - 1;
        if (lane == leader) atomicAdd(&g_bcnt[d], __popc(m));
    }
}

__global__ void bucket_scan_kernel() {
    if (threadIdx.x == 0) {
        int run = 0;
        for (int d = 0; d <= MAXDEG; d++) { g_boff[d] = run; run += g_bcnt[d]; }
    }
}

__global__ void csr_fill_kernel(const int* __restrict__ ei) {
    int e = blockIdx.x * 256 + threadIdx.x;
    if (e >= NE) return;
    int t = ei[NE + e];
    int pos = g_off[t] + atomicAdd(&g_cur[t], 1);
    g_csr[pos] = (g_rel[e] << 28) | ei[e];
}

__global__ void bucket_fill_kernel() {
    int n = blockIdx.x * 256 + threadIdx.x;
    int lane = threadIdx.x & 31;
    bool valid = n < NN;
    int d = valid ? g_deg[n] : 0;
    unsigned vm = __ballot_sync(0xffffffffu, valid);
    unsigned m = __match_any_sync(0xffffffffu, d) & vm;
    if (!valid) return;
    int leader = __ffs(m) - 1;
    int rank = __popc(m & ((1u << lane) - 1));
    int base = 0;
    if (lane == leader) base = atomicAdd(&g_bcur[d], __popc(m));
    base = __shfl_sync(0xffffffffu, base, leader);
    g_bnodes[g_boff[d] + base + rank] = n;
}

// ---------------- RGCN gather: agg[n][r] = inv[n,r] * sum_{e:rel=r} relu(h[src]) ----------------
__global__ __launch_bounds__(256) void rgcn_gather_kernel() {
    int tid = threadIdx.x;
    int node = blockIdx.x * 4 + (tid >> 6);
    if (node >= NN) return;
    int dim = tid & 63;
    int beg = g_off[node];
    int end = beg + g_indeg[node];
    float a0 = 0.f, a1 = 0.f, a2 = 0.f, a3 = 0.f;
    int i = beg;
    for (; i + 2 <= end; i += 2) {
        int p0 = __ldg(&g_csr[i]), p1 = __ldg(&g_csr[i + 1]);
        int r0 = p0 >> 28, r1 = p1 >> 28;
        float v0 = fmaxf(g_h[(p0 & 0x0FFFFFFF) * NH + dim], 0.f);
        float v1 = fmaxf(g_h[(p1 & 0x0FFFFFFF) * NH + dim], 0.f);
        a0 += (r0 == 0 ? v0 : 0.f) + (r1 == 0 ? v1 : 0.f);
        a1 += (r0 == 1 ? v0 : 0.f) + (r1 == 1 ? v1 : 0.f);
        a2 += (r0 == 2 ? v0 : 0.f) + (r1 == 2 ? v1 : 0.f);
        a3 += (r0 == 3 ? v0 : 0.f) + (r1 == 3 ? v1 : 0.f);
    }
    for (; i < end; i++) {
        int p = __ldg(&g_csr[i]);
        int r = p >> 28;
        float v = fmaxf(g_h[(p & 0x0FFFFFFF) * NH + dim], 0.f);
        a0 += (r == 0 ? v : 0.f); a1 += (r == 1 ? v : 0.f);
        a2 += (r == 2 ? v : 0.f); a3 += (r == 3 ? v : 0.f);
    }
    const float* iw = g_invw + node * NREL;
    float* o = g_agg + ((size_t)node * NREL) * NH + dim;
    o[0 * NH] = a0 * iw[0];
    o[1 * NH] = a1 * iw[1];
    o[2 * NH] = a2 * iw[2];
    o[3 * NH] = a3 * iw[3];
}

// ---------------- RGCN GEMM: hmid = [agg0|agg1|agg2|agg3|relu(h)] @ [W0;W1;W2;W3;Wroot] + b ----------------
__global__ __launch_bounds__(128) void rgcn_gemm_kernel(const float* __restrict__ W,
                                                        const float* __restrict__ Wroot,
                                                        const float* __restrict__ bias) {
    __shared__ float AsT[NH][128];   // 32 KB (transposed K-chunk)
    __shared__ float Bs[NH * NH];    // 16 KB
    int tid = threadIdx.x;
    int row = blockIdx.x * 128 + tid;
    int ty = tid >> 3, tx = tid & 7;

    float acc[8][8];
#pragma unroll
    for (int i = 0; i < 8; i++)
#pragma unroll
        for (int j = 0; j < 8; j++) acc[i][j] = 0.f;

    for (int chunk = 0; chunk < 5; chunk++) {
        if (chunk) __syncthreads();
        const float4* B4 = (const float4*)((chunk < 4) ? (W + chunk * NH * NH) : Wroot);
        float4* Bs4 = (float4*)Bs;
#pragma unroll
        for (int i = 0; i < 8; i++) Bs4[i * 128 + tid] = B4[i * 128 + tid];
        if (row < NN) {
            const float4* ar = (chunk < 4)
                ? (const float4*)(g_agg + ((size_t)row * NREL + chunk) * NH)
                : (const float4*)(g_h + (size_t)row * NH);
            bool rl = (chunk == 4);
#pragma unroll
            for (int c4 = 0; c4 < 16; c4++) {
                float4 v = ar[c4];
                if (rl) { v.x = fmaxf(v.x, 0.f); v.y = fmaxf(v.y, 0.f);
                          v.z = fmaxf(v.z, 0.f); v.w = fmaxf(v.w, 0.f); }
                AsT[c4 * 4 + 0][tid] = v.x; AsT[c4 * 4 + 1][tid] = v.y;
                AsT[c4 * 4 + 2][tid] = v.z; AsT[c4 * 4 + 3][tid] = v.w;
            }
        } else {
#pragma unroll
            for (int c = 0; c < NH; c++) AsT[c][tid] = 0.f;
        }
        __syncthreads();
#pragma unroll 4
        for (int k = 0; k < NH; k++) {
            float4 a0 = *(const float4*)&AsT[k][ty * 8];
            float4 a1 = *(const float4*)&AsT[k][ty * 8 + 4];
            float4 b0 = *(const float4*)&Bs[k * NH + tx * 8];
            float4 b1 = *(const float4*)&Bs[k * NH + tx * 8 + 4];
            float av[8] = {a0.x, a0.y, a0.z, a0.w, a1.x, a1.y, a1.z, a1.w};
            float bv[8] = {b0.x, b0.y, b0.z, b0.w, b1.x, b1.y, b1.z, b1.w};
#pragma unroll
            for (int i = 0; i < 8; i++)
#pragma unroll
                for (int j = 0; j < 8; j++) acc[i][j] += av[i] * bv[j];
        }
    }

    int rbase = blockIdx.x * 128 + ty * 8;
    float b0 = bias[tx * 8 + 0], b1 = bias[tx * 8 + 1], b2 = bias[tx * 8 + 2], b3 = bias[tx * 8 + 3];
    float b4 = bias[tx * 8 + 4], b5 = bias[tx * 8 + 5], b6 = bias[tx * 8 + 6], b7 = bias[tx * 8 + 7];
#pragma unroll
    for (int i = 0; i < 8; i++) {
        int r = rbase + i;
        if (r < NN) {
            float4* o = (float4*)(g_hmid + (size_t)r * NH + tx * 8);
            o[0] = make_float4(acc[i][0] + b0, acc[i][1] + b1, acc[i][2] + b2, acc[i][3] + b3);
            o[1] = make_float4(acc[i][4] + b4, acc[i][5] + b5, acc[i][6] + b6, acc[i][7] + b7);
        }
    }
}

// ---------------- MFConv gather: aggm[t] = sum relu(hmid[src]) ----------------
__global__ __launch_bounds__(256) void mf_gather_kernel() {
    int tid = threadIdx.x;
    int node = blockIdx.x * 4 + (tid >> 6);
    if (node >= NN) return;
    int dim = tid & 63;
    int beg = g_off[node];
    int end = beg + g_indeg[node];
    float acc = 0.f;
    int i = beg;
    for (; i + 4 <= end; i += 4) {
        int s0 = __ldg(&g_csr[i]) & 0x0FFFFFFF, s1 = __ldg(&g_csr[i + 1]) & 0x0FFFFFFF;
        int s2 = __ldg(&g_csr[i + 2]) & 0x0FFFFFFF, s3 = __ldg(&g_csr[i + 3]) & 0x0FFFFFFF;
        acc += fmaxf(g_hmid[s0 * NH + dim], 0.f) + fmaxf(g_hmid[s1 * NH + dim], 0.f)
             + fmaxf(g_hmid[s2 * NH + dim], 0.f) + fmaxf(g_hmid[s3 * NH + dim], 0.f);
    }
    for (; i < end; i++)
        acc += fmaxf(g_hmid[(__ldg(&g_csr[i]) & 0x0FFFFFFF) * NH + dim], 0.f);
    g_aggm[node * NH + dim] = acc;
}

// ---------------- MFConv fused GEMM: h[n] = [aggm | relu(hmid)] @ [Wl[d]; Wr[d]] + bl[d] ----------------
__global__ __launch_bounds__(128) void mf_gemm_kernel(const float* __restrict__ Wl,
                                                      const float* __restrict__ bl,
                                                      const float* __restrict__ Wr) {
    __shared__ float AsT[2 * NH][64];   // 32 KB
    __shared__ float Bs[2 * NH * NH];   // 32 KB
    __shared__ int nodes[64];
    int d = blockIdx.y;
    int cnt = g_bcnt[d];
    int t0 = blockIdx.x * 64;
    if (t0 >= cnt) return;
    int tid = threadIdx.x;
    if (tid < 64) {
        int idx = t0 + tid;
        nodes[tid] = (idx < cnt) ? g_bnodes[g_boff[d] + idx] : -1;
    }
    // B = [Wl[d]; Wr[d]] stacked (K=128 rows x 64 cols)
    {
        const float4* Bl4 = (const float4*)(Wl + d * NH * NH);
        const float4* Br4 = (const float4*)(Wr + d * NH * NH);
        float4* Bs4 = (float4*)Bs;
#pragma unroll
        for (int i = 0; i < 8; i++) Bs4[i * 128 + tid] = Bl4[i * 128 + tid];
#pragma unroll
        for (int i = 0; i < 8; i++) Bs4[1024 + i * 128 + tid] = Br4[i * 128 + tid];
    }
    __syncthreads();
    // A: rows = 64 bucket nodes; k<64 -> aggm, k>=64 -> relu(hmid)
    {
        int r = tid & 63, half = tid >> 6;
        int n = nodes[r];
        const float4* ar = nullptr;
        if (n >= 0)
            ar = half ? (const float4*)(g_hmid + (size_t)n * NH)
                      : (const float4*)(g_aggm + (size_t)n * NH);
#pragma unroll
        for (int c4 = 0; c4 < 16; c4++) {
            float4 v = (n >= 0) ? ar[c4] : make_float4(0.f, 0.f, 0.f, 0.f);
            if (half) { v.x = fmaxf(v.x, 0.f); v.y = fmaxf(v.y, 0.f);
                        v.z = fmaxf(v.z, 0.f); v.w = fmaxf(v.w, 0.f); }
            int k = half * NH + c4 * 4;
            AsT[k + 0][r] = v.x; AsT[k + 1][r] = v.y;
            AsT[k + 2][r] = v.z; AsT[k + 3][r] = v.w;
        }
    }
    __syncthreads();

    int ty = tid >> 3, tx = tid & 7;   // rows ty*4..+3, cols tx*8..+7
    float acc[4][8];
#pragma unroll
    for (int i = 0; i < 4; i++)
#pragma unroll
        for (int j = 0; j < 8; j++) acc[i][j] = 0.f;

#pragma unroll 4
    for (int k = 0; k < 2 * NH; k++) {
        float4 a = *(const float4*)&AsT[k][ty * 4];
        float4 b0 = *(const float4*)&Bs[k * NH + tx * 8];
        float4 b1 = *(const float4*)&Bs[k * NH + tx * 8 + 4];
        float av[4] = {a.x, a.y, a.z, a.w};
        float bv[8] = {b0.x, b0.y, b0.z, b0.w, b1.x, b1.y, b1.z, b1.w};
#pragma unroll
        for (int i = 0; i < 4; i++)
#pragma unroll
            for (int j = 0; j < 8; j++) acc[i][j] += av[i] * bv[j];
    }

    const float* bb = bl + d * NH + tx * 8;
    float e0 = bb[0], e1 = bb[1], e2 = bb[2], e3 = bb[3];
    float e4 = bb[4], e5 = bb[5], e6 = bb[6], e7 = bb[7];
#pragma unroll
    for (int i = 0; i < 4; i++) {
        int n = nodes[ty * 4 + i];
        if (n >= 0) {
            float4* o = (float4*)(g_h + (size_t)n * NH + tx * 8);
            o[0] = make_float4(acc[i][0] + e0, acc[i][1] + e1, acc[i][2] + e2, acc[i][3] + e3);
            o[1] = make_float4(acc[i][4] + e4, acc[i][5] + e5, acc[i][6] + e6, acc[i][7] + e7);
        }
    }
}

// ---------------- global add pool (4-node coalesced atomics; batch is sorted) ----------------
__global__ void pool_kernel(const int* __restrict__ batch) {
    int i = blockIdx.x * 256 + threadIdx.x;
    int grp = i >> 6;
    if (grp * 4 >= NN) return;
    int dim = i & 63;
    int n0 = grp * 4;
    int curb = batch[n0];
    float vsum = g_h[(size_t)n0 * NH + dim];
#pragma unroll
    for (int j = 1; j < 4; j++) {
        int n = n0 + j;
        if (n >= NN) break;
        int b = batch[n];
        float v = g_h[(size_t)n * NH + dim];
        if (b == curb) vsum += v;
        else { atomicAdd(&g_pool[curb * NH + dim], vsum); curb = b; vsum = v; }
    }
    atomicAdd(&g_pool[curb * NH + dim], vsum);
}

// ---------------- head MLP: relu(g@l1+b1)@l2+b2 ----------------
__global__ __launch_bounds__(256) void mlp_kernel(const float* __restrict__ l1w, const float* __restrict__ l1b,
                                                  const float* __restrict__ l2w, const float* __restrict__ l2b,
                                                  float* __restrict__ out) {
    __shared__ float s1[NH * NH];
    __shared__ float s2[NH * NO];
    __shared__ float sg[8][NH];
    int tid = threadIdx.x, lane = tid & 31, w = tid >> 5;
#pragma unroll
    for (int i = 0; i < 16; i++) s1[i * 256 + tid] = l1w[i * 256 + tid];
#pragma unroll
    for (int i = 0; i < 4; i++) s2[i * 256 + tid] = l2w[i * 256 + tid];
    int gidx = blockIdx.x * 8 + w;
    sg[w][lane] = g_pool[gidx * NH + lane];
    sg[w][lane + 32] = g_pool[gidx * NH + lane + 32];
    __syncthreads();
    float t0 = l1b[lane], t1 = l1b[lane + 32];
#pragma unroll 8
    for (int k = 0; k < NH; k++) {
        float gv = sg[w][k];
        t0 += gv * s1[k * NH + lane];
        t1 += gv * s1[k * NH + lane + 32];
    }
    t0 = fmaxf(t0, 0.f); t1 = fmaxf(t1, 0.f);
    __syncwarp();
    sg[w][lane] = t0; sg[w][lane + 32] = t1;
    __syncwarp();
    if (lane < NO) {
        float acc = l2b[lane];
#pragma unroll 8
        for (int j = 0; j < NH; j++) acc += sg[w][j] * s2[j * NO + lane];
        out[gidx * NO + lane] = acc;
    }
}

// ---------------- launch ----------------
extern "C" void kernel_launch(void* const* d_in, const int* in_sizes, int n_in,
                              void* d_out, int out_size) {
    const float *x, *ea, *emb, *l1w, *l1b, *l2w, *l2b;
    const int *ei, *batch;
    const float *rw[2], *rro[2], *rb[2], *wl[2], *bll[2], *wr[2];

    if (in_sizes[1] == NE * NREL) {
        // dict order
        x = (const float*)d_in[0];  ea = (const float*)d_in[1];
        ei = (const int*)d_in[2];   batch = (const int*)d_in[3];
        emb = (const float*)d_in[4];
        l1w = (const float*)d_in[5]; l1b = (const float*)d_in[6];
        l2w = (const float*)d_in[7]; l2b = (const float*)d_in[8];
        for (int b = 0; b < 2; b++) {
            int k = 9 + 6 * b;
            rw[b]  = (const float*)d_in[k + 0];
            rro[b] = (const float*)d_in[k + 1];
            rb[b]  = (const float*)d_in[k + 2];
            wl[b]  = (const float*)d_in[k + 3];
            bll[b] = (const float*)d_in[k + 4];
            wr[b]  = (const float*)d_in[k + 5];
        }
    } else {
        // reference-arg order
        x = (const float*)d_in[0];  ei = (const int*)d_in[1];
        ea = (const float*)d_in[2]; batch = (const int*)d_in[3];
        emb = (const float*)d_in[4];
        for (int b = 0; b < 2; b++) {
            int k = 5 + 6 * b;
            rw[b]  = (const float*)d_in[k + 0];
            rro[b] = (const float*)d_in[k + 1];
            rb[b]  = (const float*)d_in[k + 2];
            wl[b]  = (const float*)d_in[k + 3];
            bll[b] = (const float*)d_in[k + 4];
            wr[b]  = (const float*)d_in[k + 5];
        }
        l1w = (const float*)d_in[17]; l1b = (const float*)d_in[18];
        l2w = (const float*)d_in[19]; l2b = (const float*)d_in[20];
    }
    float* out = (float*)d_out;

    zero_kernel<<<(NN * NREL + 255) / 256, 256>>>();
    node_init_kernel<<<(NN + 127) / 128, 128>>>(x, emb);
    edge_prep_kernel<<<(NE + 255) / 256, 256>>>(ea, ei);
    node_meta_kernel<<<(NN + 255) / 256, 256>>>();
    bucket_scan_kernel<<<1, 32>>>();
    csr_fill_kernel<<<(NE + 255) / 256, 256>>>(ei);
    bucket_fill_kernel<<<(NN + 255) / 256, 256>>>();

    for (int b = 0; b < 2; b++) {
        rgcn_gather_kernel<<<(NN + 3) / 4, 256>>>();
        rgcn_gemm_kernel<<<(NN + 127) / 128, 128>>>(rw[b], rro[b], rb[b]);
        mf_gather_kernel<<<(NN + 3) / 4, 256>>>();
        mf_gemm_kernel<<<dim3((NN + 63) / 64, MAXDEG + 1), 128>>>(wl[b], bll[b], wr[b]);
    }

    pool_kernel<<<(NN * NH / 4 + 255) / 256, 256>>>(batch);
    mlp_kernel<<<NG / 8, 256>>>(l1w, l1b, l2w, l2b, out);
}

// round 4
// speedup vs baseline: 1.4567x; 1.2560x over previous
#include <cuda_runtime.h>
#include <cuda_bf16.h>
#include <cstdint>

#define NN 50000
#define NE 800000
#define NG 1024
#define NFEAT 32
#define NREL 4
#define NH 64
#define NO 16
#define MAXDEG 10

// padded bf16 tile stride (elements): 72 -> 144B rows, conflict-free fragment LDS
#define AST 72
// dynamic smem layout (bytes)
#define OFF_NODES 0
#define OFF_AHI   1024
#define OFF_ALO   (OFF_AHI + 128 * AST * 2)   // 19456
#define OFF_BHI   (OFF_ALO + 128 * AST * 2)   // 37888
#define OFF_BLO   (OFF_BHI + 64 * AST * 2)    // 47104
#define SMEM_SZ   (OFF_BLO + 64 * AST * 2)    // 56320

// ---------------- scratch (device globals) ----------------
__device__ float g_h[NN * NH];
__device__ float g_hmid[NN * NH];
__device__ float g_aggm[NN * NH];
__device__ float g_agg[NN * NREL * NH];
__device__ float g_pool[NG * NH];
__device__ float g_invw[NN * NREL];
__device__ int   g_cnt[NN * NREL];
__device__ int   g_indeg[NN];
__device__ int   g_off[NN];
__device__ int   g_cur[NN];
__device__ int   g_csr[NE];
__device__ int   g_rel[NE];
__device__ int   g_deg[NN];
__device__ int   g_bcnt[MAXDEG + 1];
__device__ int   g_boff[MAXDEG + 1];
__device__ int   g_bcur[MAXDEG + 1];
__device__ int   g_bnodes[NN];
__device__ int   g_total;

// ---------------- mma.sync helper ----------------
static __device__ __forceinline__ void mma16816(float* c, const uint32_t* a, const uint32_t* b) {
    asm volatile(
        "mma.sync.aligned.m16n8k16.row.col.f32.bf16.bf16.f32 "
        "{%0,%1,%2,%3}, {%4,%5,%6,%7}, {%8,%9}, {%0,%1,%2,%3};\n"
        : "+f"(c[0]), "+f"(c[1]), "+f"(c[2]), "+f"(c[3])
        : "r"(a[0]), "r"(a[1]), "r"(a[2]), "r"(a[3]), "r"(b[0]), "r"(b[1]));
}
static __device__ __forceinline__ uint32_t lds_u32(const __nv_bfloat16* p) {
    return *reinterpret_cast<const uint32_t*>(p);
}

// split one float4 (row segment of 4 k-values) into bf16 hi/lo into padded tiles
static __device__ __forceinline__ void split_store4(__nv_bfloat16* Ah, __nv_bfloat16* Al,
                                                    int row, int k, float4 v) {
    __nv_bfloat16 hx = __float2bfloat16_rn(v.x);
    __nv_bfloat16 hy = __float2bfloat16_rn(v.y);
    __nv_bfloat16 hz = __float2bfloat16_rn(v.z);
    __nv_bfloat16 hw = __float2bfloat16_rn(v.w);
    __nv_bfloat16 lx = __float2bfloat16_rn(v.x - __bfloat162float(hx));
    __nv_bfloat16 ly = __float2bfloat16_rn(v.y - __bfloat162float(hy));
    __nv_bfloat16 lz = __float2bfloat16_rn(v.z - __bfloat162float(hz));
    __nv_bfloat16 lw = __float2bfloat16_rn(v.w - __bfloat162float(hw));
    __nv_bfloat162* ph = reinterpret_cast<__nv_bfloat162*>(Ah + row * AST + k);
    __nv_bfloat162* pl = reinterpret_cast<__nv_bfloat162*>(Al + row * AST + k);
    ph[0] = __nv_bfloat162(hx, hy); ph[1] = __nv_bfloat162(hz, hw);
    pl[0] = __nv_bfloat162(lx, ly); pl[1] = __nv_bfloat162(lz, lw);
}

// transpose-load 64x64 fp32 weight chunk [k][n] -> [n][k] bf16 hi/lo padded tiles
static __device__ __forceinline__ void load_b_chunk(__nv_bfloat16* Bh, __nv_bfloat16* Bl,
                                                    const float* __restrict__ bsrc, int tid) {
#pragma unroll
    for (int i = 0; i < 32; i++) {
        int idx = i * 128 + tid;
        int k = idx >> 6, n = idx & 63;
        float val = __ldg(&bsrc[k * 64 + n]);
        __nv_bfloat16 hb = __float2bfloat16_rn(val);
        __nv_bfloat16 lb = __float2bfloat16_rn(val - __bfloat162float(hb));
        Bh[n * AST + k] = hb;
        Bl[n * AST + k] = lb;
    }
}

// warp-level 32x64 mma over one K=64 chunk; acc[2][8][4]
static __device__ __forceinline__ void mma_chunk(float acc[2][8][4],
                                                 const __nv_bfloat16* Ah, const __nv_bfloat16* Al,
                                                 const __nv_bfloat16* Bh, const __nv_bfloat16* Bl,
                                                 int wid, int lane) {
    int g = lane >> 2, t = lane & 3;
#pragma unroll
    for (int ks = 0; ks < 4; ks++) {
        int kb = ks * 16 + 2 * t;
        uint32_t ah[2][4], al[2][4];
#pragma unroll
        for (int mt = 0; mt < 2; mt++) {
            const __nv_bfloat16* ph = Ah + (wid * 32 + mt * 16 + g) * AST + kb;
            const __nv_bfloat16* pl = Al + (wid * 32 + mt * 16 + g) * AST + kb;
            ah[mt][0] = lds_u32(ph);            ah[mt][1] = lds_u32(ph + 8 * AST);
            ah[mt][2] = lds_u32(ph + 8);        ah[mt][3] = lds_u32(ph + 8 * AST + 8);
            al[mt][0] = lds_u32(pl);            al[mt][1] = lds_u32(pl + 8 * AST);
            al[mt][2] = lds_u32(pl + 8);        al[mt][3] = lds_u32(pl + 8 * AST + 8);
        }
#pragma unroll
        for (int nt = 0; nt < 8; nt++) {
            const __nv_bfloat16* qh = Bh + (nt * 8 + g) * AST + kb;
            const __nv_bfloat16* ql = Bl + (nt * 8 + g) * AST + kb;
            uint32_t bh[2] = {lds_u32(qh), lds_u32(qh + 8)};
            uint32_t bl[2] = {lds_u32(ql), lds_u32(ql + 8)};
#pragma unroll
            for (int mt = 0; mt < 2; mt++) {
                mma16816(acc[mt][nt], ah[mt], bh);
                mma16816(acc[mt][nt], ah[mt], bl);
                mma16816(acc[mt][nt], al[mt], bh);
            }
        }
    }
}

// ---------------- zero scratch ----------------
__global__ void zero_kernel() {
    int i = blockIdx.x * 256 + threadIdx.x;
    if (i < NN * NREL) g_cnt[i] = 0;
    if (i < NN) g_cur[i] = 0;
    if (i < NG * NH) g_pool[i] = 0.f;
    if (i <= MAXDEG) { g_bcnt[i] = 0; g_bcur[i] = 0; }
    if (i == 0) g_total = 0;
}

// ---------------- node init ----------------
__global__ void node_init_kernel(const float* __restrict__ x, const float* __restrict__ emb) {
    int n = blockIdx.x * 128 + threadIdx.x;
    if (n >= NN) return;
    const float4* xr = (const float4*)(x + (size_t)n * NFEAT);
    float best = -1e30f; int bi = 0;
#pragma unroll
    for (int q = 0; q < NFEAT / 4; q++) {
        float4 v = xr[q];
        if (v.x > best) { best = v.x; bi = q * 4 + 0; }
        if (v.y > best) { best = v.y; bi = q * 4 + 1; }
        if (v.z > best) { best = v.z; bi = q * 4 + 2; }
        if (v.w > best) { best = v.w; bi = q * 4 + 3; }
    }
    const float4* er = (const float4*)(emb + bi * NH);
    float4* hr = (float4*)(g_h + (size_t)n * NH);
#pragma unroll
    for (int q = 0; q < NH / 4; q++) hr[q] = er[q];
}

// ---------------- edge prep ----------------
__global__ void edge_prep_kernel(const float* __restrict__ ea, const int* __restrict__ ei) {
    int e = blockIdx.x * 256 + threadIdx.x;
    if (e >= NE) return;
    float4 a = ((const float4*)ea)[e];
    int rel = 0; float best = a.x;
    if (a.y > best) { best = a.y; rel = 1; }
    if (a.z > best) { best = a.z; rel = 2; }
    if (a.w > best) { best = a.w; rel = 3; }
    g_rel[e] = rel;
    atomicAdd(&g_cnt[ei[NE + e] * NREL + rel], 1);
}

// ---------------- node meta ----------------
__global__ void node_meta_kernel() {
    int n = blockIdx.x * 256 + threadIdx.x;
    int lane = threadIdx.x & 31;
    bool valid = n < NN;
    int c0 = 0, c1 = 0, c2 = 0, c3 = 0;
    if (valid) {
        c0 = g_cnt[n * NREL + 0]; c1 = g_cnt[n * NREL + 1];
        c2 = g_cnt[n * NREL + 2]; c3 = g_cnt[n * NREL + 3];
    }
    int ind = c0 + c1 + c2 + c3;
    if (valid) {
        g_invw[n * NREL + 0] = c0 ? 1.0f / (float)c0 : 0.f;
        g_invw[n * NREL + 1] = c1 ? 1.0f / (float)c1 : 0.f;
        g_invw[n * NREL + 2] = c2 ? 1.0f / (float)c2 : 0.f;
        g_invw[n * NREL + 3] = c3 ? 1.0f / (float)c3 : 0.f;
        g_indeg[n] = ind;
    }
    int incl = ind;
#pragma unroll
    for (int o = 1; o < 32; o <<= 1) {
        int t = __shfl_up_sync(0xffffffffu, incl, o);
        if (lane >= o) incl += t;
    }
    int wsum = __shfl_sync(0xffffffffu, incl, 31);
    int base = 0;
    if (lane == 0) base = atomicAdd(&g_total, wsum);
    base = __shfl_sync(0xffffffffu, base, 0);
    if (valid) g_off[n] = base + incl - ind;
    int d = min(ind, MAXDEG);
    if (valid) g_deg[n] = d;
    unsigned vm = __ballot_sync(0xffffffffu, valid);
    unsigned m = __match_any_sync(0xffffffffu, d) & vm;
    if (valid) {
        int leader = __ffs(m) - 1;
        if (lane == leader) atomicAdd(&g_bcnt[d], __popc(m));
    }
}

__global__ void bucket_scan_kernel() {
    if (threadIdx.x == 0) {
        int run = 0;
        for (int d = 0; d <= MAXDEG; d++) { g_boff[d] = run; run += g_bcnt[d]; }
    }
}

__global__ void csr_fill_kernel(const int* __restrict__ ei) {
    int e = blockIdx.x * 256 + threadIdx.x;
    if (e >= NE) return;
    int t = ei[NE + e];
    int pos = g_off[t] + atomicAdd(&g_cur[t], 1);
    g_csr[pos] = (g_rel[e] << 28) | ei[e];
}

__global__ void bucket_fill_kernel() {
    int n = blockIdx.x * 256 + threadIdx.x;
    int lane = threadIdx.x & 31;
    bool valid = n < NN;
    int d = valid ? g_deg[n] : 0;
    unsigned vm = __ballot_sync(0xffffffffu, valid);
    unsigned m = __match_any_sync(0xffffffffu, d) & vm;
    if (!valid) return;
    int leader = __ffs(m) - 1;
    int rank = __popc(m & ((1u << lane) - 1));
    int base = 0;
    if (lane == leader) base = atomicAdd(&g_bcur[d], __popc(m));
    base = __shfl_sync(0xffffffffu, base, leader);
    g_bnodes[g_boff[d] + base + rank] = n;
}

// ---------------- RGCN gather ----------------
__global__ __launch_bounds__(256) void rgcn_gather_kernel() {
    int tid = threadIdx.x;
    int node = blockIdx.x * 4 + (tid >> 6);
    if (node >= NN) return;
    int dim = tid & 63;
    int beg = g_off[node];
    int end = beg + g_indeg[node];
    float a0 = 0.f, a1 = 0.f, a2 = 0.f, a3 = 0.f;
    int i = beg;
    for (; i + 2 <= end; i += 2) {
        int p0 = __ldg(&g_csr[i]), p1 = __ldg(&g_csr[i + 1]);
        int r0 = p0 >> 28, r1 = p1 >> 28;
        float v0 = fmaxf(g_h[(p0 & 0x0FFFFFFF) * NH + dim], 0.f);
        float v1 = fmaxf(g_h[(p1 & 0x0FFFFFFF) * NH + dim], 0.f);
        a0 += (r0 == 0 ? v0 : 0.f) + (r1 == 0 ? v1 : 0.f);
        a1 += (r0 == 1 ? v0 : 0.f) + (r1 == 1 ? v1 : 0.f);
        a2 += (r0 == 2 ? v0 : 0.f) + (r1 == 2 ? v1 : 0.f);
        a3 += (r0 == 3 ? v0 : 0.f) + (r1 == 3 ? v1 : 0.f);
    }
    for (; i < end; i++) {
        int p = __ldg(&g_csr[i]);
        int r = p >> 28;
        float v = fmaxf(g_h[(p & 0x0FFFFFFF) * NH + dim], 0.f);
        a0 += (r == 0 ? v : 0.f); a1 += (r == 1 ? v : 0.f);
        a2 += (r == 2 ? v : 0.f); a3 += (r == 3 ? v : 0.f);
    }
    const float* iw = g_invw + node * NREL;
    float* o = g_agg + ((size_t)node * NREL) * NH + dim;
    o[0 * NH] = a0 * iw[0];
    o[1 * NH] = a1 * iw[1];
    o[2 * NH] = a2 * iw[2];
    o[3 * NH] = a3 * iw[3];
}

// ---------------- RGCN GEMM via mma.sync bf16-split (5 K-chunks of 64) ----------------
__global__ __launch_bounds__(128) void rgcn_gemm_tc(const float* __restrict__ W,
                                                    const float* __restrict__ Wroot,
                                                    const float* __restrict__ bias) {
    extern __shared__ __align__(16) char smem[];
    __nv_bfloat16* Ah = (__nv_bfloat16*)(smem + OFF_AHI);
    __nv_bfloat16* Al = (__nv_bfloat16*)(smem + OFF_ALO);
    __nv_bfloat16* Bh = (__nv_bfloat16*)(smem + OFF_BHI);
    __nv_bfloat16* Bl = (__nv_bfloat16*)(smem + OFF_BLO);
    int tid = threadIdx.x, wid = tid >> 5, lane = tid & 31;
    int row = blockIdx.x * 128 + tid;

    float acc[2][8][4];
#pragma unroll
    for (int a = 0; a < 2; a++)
#pragma unroll
        for (int b = 0; b < 8; b++)
#pragma unroll
            for (int c = 0; c < 4; c++) acc[a][b][c] = 0.f;

    for (int c = 0; c < 5; c++) {
        if (c) __syncthreads();
        if (row < NN) {
            const float4* src = (c < 4)
                ? (const float4*)(g_agg + ((size_t)row * NREL + c) * NH)
                : (const float4*)(g_h + (size_t)row * NH);
            bool rl = (c == 4);
#pragma unroll
            for (int q = 0; q < 16; q++) {
                float4 v = src[q];
                if (rl) { v.x = fmaxf(v.x, 0.f); v.y = fmaxf(v.y, 0.f);
                          v.z = fmaxf(v.z, 0.f); v.w = fmaxf(v.w, 0.f); }
                split_store4(Ah, Al, tid, q * 4, v);
            }
        } else {
#pragma unroll
            for (int q = 0; q < 16; q++)
                split_store4(Ah, Al, tid, q * 4, make_float4(0.f, 0.f, 0.f, 0.f));
        }
        load_b_chunk(Bh, Bl, (c < 4) ? (W + c * NH * NH) : Wroot, tid);
        __syncthreads();
        mma_chunk(acc, Ah, Al, Bh, Bl, wid, lane);
    }

    // epilogue: D rows base+mt*16+{g,g+8}, cols nt*8+{2t,2t+1}
    int g = lane >> 2, t = lane & 3;
#pragma unroll
    for (int mt = 0; mt < 2; mt++) {
        int r0 = blockIdx.x * 128 + wid * 32 + mt * 16 + g;
        int r1 = r0 + 8;
#pragma unroll
        for (int nt = 0; nt < 8; nt++) {
            int col = nt * 8 + 2 * t;
            float b0 = __ldg(&bias[col]), b1 = __ldg(&bias[col + 1]);
            if (r0 < NN)
                *(float2*)(g_hmid + (size_t)r0 * NH + col) =
                    make_float2(acc[mt][nt][0] + b0, acc[mt][nt][1] + b1);
            if (r1 < NN)
                *(float2*)(g_hmid + (size_t)r1 * NH + col) =
                    make_float2(acc[mt][nt][2] + b0, acc[mt][nt][3] + b1);
        }
    }
}

// ---------------- MFConv gather ----------------
__global__ __launch_bounds__(256) void mf_gather_kernel() {
    int tid = threadIdx.x;
    int node = blockIdx.x * 4 + (tid >> 6);
    if (node >= NN) return;
    int dim = tid & 63;
    int beg = g_off[node];
    int end = beg + g_indeg[node];
    float acc = 0.f;
    int i = beg;
    for (; i + 4 <= end; i += 4) {
        int s0 = __ldg(&g_csr[i]) & 0x0FFFFFFF, s1 = __ldg(&g_csr[i + 1]) & 0x0FFFFFFF;
        int s2 = __ldg(&g_csr[i + 2]) & 0x0FFFFFFF, s3 = __ldg(&g_csr[i + 3]) & 0x0FFFFFFF;
        acc += fmaxf(g_hmid[s0 * NH + dim], 0.f) + fmaxf(g_hmid[s1 * NH + dim], 0.f)
             + fmaxf(g_hmid[s2 * NH + dim], 0.f) + fmaxf(g_hmid[s3 * NH + dim], 0.f);
    }
    for (; i < end; i++)
        acc += fmaxf(g_hmid[(__ldg(&g_csr[i]) & 0x0FFFFFFF) * NH + dim], 0.f);
    g_aggm[node * NH + dim] = acc;
}

// ---------------- MFConv GEMM via mma.sync (bucketed, 2 K-chunks of 64) ----------------
__global__ __launch_bounds__(128) void mf_gemm_tc(const float* __restrict__ Wl,
                                                  const float* __restrict__ blv,
                                                  const float* __restrict__ Wr) {
    int d = blockIdx.y;
    int cnt = g_bcnt[d];
    int t0 = blockIdx.x * 128;
    if (t0 >= cnt) return;

    extern __shared__ __align__(16) char smem[];
    int* nodes = (int*)(smem + OFF_NODES);
    __nv_bfloat16* Ah = (__nv_bfloat16*)(smem + OFF_AHI);
    __nv_bfloat16* Al = (__nv_bfloat16*)(smem + OFF_ALO);
    __nv_bfloat16* Bh = (__nv_bfloat16*)(smem + OFF_BHI);
    __nv_bfloat16* Bl = (__nv_bfloat16*)(smem + OFF_BLO);
    int tid = threadIdx.x, wid = tid >> 5, lane = tid & 31;
    {
        int idx = t0 + tid;
        nodes[tid] = (idx < cnt) ? g_bnodes[g_boff[d] + idx] : -1;
    }
    __syncthreads();
    int mynode = nodes[tid];

    float acc[2][8][4];
#pragma unroll
    for (int a = 0; a < 2; a++)
#pragma unroll
        for (int b = 0; b < 8; b++)
#pragma unroll
            for (int cc = 0; cc < 4; cc++) acc[a][b][cc] = 0.f;

    for (int c = 0; c < 2; c++) {
        if (c) __syncthreads();
        if (mynode >= 0) {
            const float4* src = c ? (const float4*)(g_hmid + (size_t)mynode * NH)
                                  : (const float4*)(g_aggm + (size_t)mynode * NH);
            bool rl = (c == 1);
#pragma unroll
            for (int q = 0; q < 16; q++) {
                float4 v = src[q];
                if (rl) { v.x = fmaxf(v.x, 0.f); v.y = fmaxf(v.y, 0.f);
                          v.z = fmaxf(v.z, 0.f); v.w = fmaxf(v.w, 0.f); }
                split_store4(Ah, Al, tid, q * 4, v);
            }
        } else {
#pragma unroll
            for (int q = 0; q < 16; q++)
                split_store4(Ah, Al, tid, q * 4, make_float4(0.f, 0.f, 0.f, 0.f));
        }
        load_b_chunk(Bh, Bl, (c ? Wr : Wl) + d * NH * NH, tid);
        __syncthreads();
        mma_chunk(acc, Ah, Al, Bh, Bl, wid, lane);
    }

    int g = lane >> 2, t = lane & 3;
    const float* bb = blv + d * NH;
#pragma unroll
    for (int mt = 0; mt < 2; mt++) {
        int i0 = wid * 32 + mt * 16 + g;
        int n0 = nodes[i0], n1 = nodes[i0 + 8];
#pragma unroll
        for (int nt = 0; nt < 8; nt++) {
            int col = nt * 8 + 2 * t;
            float b0 = __ldg(&bb[col]), b1 = __ldg(&bb[col + 1]);
            if (n0 >= 0)
                *(float2*)(g_h + (size_t)n0 * NH + col) =
                    make_float2(acc[mt][nt][0] + b0, acc[mt][nt][1] + b1);
            if (n1 >= 0)
                *(float2*)(g_h + (size_t)n1 * NH + col) =
                    make_float2(acc[mt][nt][2] + b0, acc[mt][nt][3] + b1);
        }
    }
}

// ---------------- global add pool ----------------
__global__ void pool_kernel(const int* __restrict__ batch) {
    int i = blockIdx.x * 256 + threadIdx.x;
    int grp = i >> 6;
    if (grp * 4 >= NN) return;
    int dim = i & 63;
    int n0 = grp * 4;
    int curb = batch[n0];
    float vsum = g_h[(size_t)n0 * NH + dim];
#pragma unroll
    for (int j = 1; j < 4; j++) {
        int n = n0 + j;
        if (n >= NN) break;
        int b = batch[n];
        float v = g_h[(size_t)n * NH + dim];
        if (b == curb) vsum += v;
        else { atomicAdd(&g_pool[curb * NH + dim], vsum); curb = b; vsum = v; }
    }
    atomicAdd(&g_pool[curb * NH + dim], vsum);
}

// ---------------- head MLP ----------------
__global__ __launch_bounds__(256) void mlp_kernel(const float* __restrict__ l1w, const float* __restrict__ l1b,
                                                  const float* __restrict__ l2w, const float* __restrict__ l2b,
                                                  float* __restrict__ out) {
    __shared__ float s1[NH * NH];
    __shared__ float s2[NH * NO];
    __shared__ float sg[8][NH];
    int tid = threadIdx.x, lane = tid & 31, w = tid >> 5;
#pragma unroll
    for (int i = 0; i < 16; i++) s1[i * 256 + tid] = l1w[i * 256 + tid];
#pragma unroll
    for (int i = 0; i < 4; i++) s2[i * 256 + tid] = l2w[i * 256 + tid];
    int gidx = blockIdx.x * 8 + w;
    sg[w][lane] = g_pool[gidx * NH + lane];
    sg[w][lane + 32] = g_pool[gidx * NH + lane + 32];
    __syncthreads();
    float t0 = l1b[lane], t1 = l1b[lane + 32];
#pragma unroll 8
    for (int k = 0; k < NH; k++) {
        float gv = sg[w][k];
        t0 += gv * s1[k * NH + lane];
        t1 += gv * s1[k * NH + lane + 32];
    }
    t0 = fmaxf(t0, 0.f); t1 = fmaxf(t1, 0.f);
    __syncwarp();
    sg[w][lane] = t0; sg[w][lane + 32] = t1;
    __syncwarp();
    if (lane < NO) {
        float acc = l2b[lane];
#pragma unroll 8
        for (int j = 0; j < NH; j++) acc += sg[w][j] * s2[j * NO + lane];
        out[gidx * NO + lane] = acc;
    }
}

// ---------------- launch ----------------
extern "C" void kernel_launch(void* const* d_in, const int* in_sizes, int n_in,
                              void* d_out, int out_size) {
    const float *x, *ea, *emb, *l1w, *l1b, *l2w, *l2b;
    const int *ei, *batch;
    const float *rw[2], *rro[2], *rb[2], *wl[2], *bll[2], *wr[2];

    if (in_sizes[1] == NE * NREL) {
        x = (const float*)d_in[0];  ea = (const float*)d_in[1];
        ei = (const int*)d_in[2];   batch = (const int*)d_in[3];
        emb = (const float*)d_in[4];
        l1w = (const float*)d_in[5]; l1b = (const float*)d_in[6];
        l2w = (const float*)d_in[7]; l2b = (const float*)d_in[8];
        for (int b = 0; b < 2; b++) {
            int k = 9 + 6 * b;
            rw[b]  = (const float*)d_in[k + 0];
            rro[b] = (const float*)d_in[k + 1];
            rb[b]  = (const float*)d_in[k + 2];
            wl[b]  = (const float*)d_in[k + 3];
            bll[b] = (const float*)d_in[k + 4];
            wr[b]  = (const float*)d_in[k + 5];
        }
    } else {
        x = (const float*)d_in[0];  ei = (const int*)d_in[1];
        ea = (const float*)d_in[2]; batch = (const int*)d_in[3];
        emb = (const float*)d_in[4];
        for (int b = 0; b < 2; b++) {
            int k = 5 + 6 * b;
            rw[b]  = (const float*)d_in[k + 0];
            rro[b] = (const float*)d_in[k + 1];
            rb[b]  = (const float*)d_in[k + 2];
            wl[b]  = (const float*)d_in[k + 3];
            bll[b] = (const float*)d_in[k + 4];
            wr[b]  = (const float*)d_in[k + 5];
        }
        l1w = (const float*)d_in[17]; l1b = (const float*)d_in[18];
        l2w = (const float*)d_in[19]; l2b = (const float*)d_in[20];
    }
    float* out = (float*)d_out;

    cudaFuncSetAttribute(rgcn_gemm_tc, cudaFuncAttributeMaxDynamicSharedMemorySize, SMEM_SZ);
    cudaFuncSetAttribute(mf_gemm_tc, cudaFuncAttributeMaxDynamicSharedMemorySize, SMEM_SZ);

    zero_kernel<<<(NN * NREL + 255) / 256, 256>>>();
    node_init_kernel<<<(NN + 127) / 128, 128>>>(x, emb);
    edge_prep_kernel<<<(NE + 255) / 256, 256>>>(ea, ei);
    node_meta_kernel<<<(NN + 255) / 256, 256>>>();
    bucket_scan_kernel<<<1, 32>>>();
    csr_fill_kernel<<<(NE + 255) / 256, 256>>>(ei);
    bucket_fill_kernel<<<(NN + 255) / 256, 256>>>();

    int mtiles = (NN + 127) / 128;
    for (int b = 0; b < 2; b++) {
        rgcn_gather_kernel<<<(NN + 3) / 4, 256>>>();
        rgcn_gemm_tc<<<mtiles, 128, SMEM_SZ>>>(rw[b], rro[b], rb[b]);
        mf_gather_kernel<<<(NN + 3) / 4, 256>>>();
        mf_gemm_tc<<<dim3(mtiles, MAXDEG + 1), 128, SMEM_SZ>>>(wl[b], bll[b], wr[b]);
    }

    pool_kernel<<<(NN * NH / 4 + 255) / 256, 256>>>(batch);
    mlp_kernel<<<NG / 8, 256>>>(l1w, l1b, l2w, l2b, out);
}

// round 5
// speedup vs baseline: 1.5301x; 1.0504x over previous
#include <cuda_runtime.h>
#include <cuda_bf16.h>
#include <cstdint>

#define NN 50000
#define NE 800000
#define NG 1024
#define NFEAT 32
#define NREL 4
#define NH 64
#define NO 16
#define MAXDEG 10

// padded bf16 tile stride (elements): 70 -> 35 words/row; fill-store bank = 3*row (coprime 32) -> conflict-free
#define AST 70
// dynamic smem layout (bytes)
#define OFF_NODES 0
#define OFF_AHI   1024
#define OFF_ALO   (OFF_AHI + 128 * AST * 2)   // 18944
#define OFF_BHI   (OFF_ALO + 128 * AST * 2)   // 36864
#define OFF_BLO   (OFF_BHI + 64 * AST * 2)    // 45824
#define SMEM_SZ   (OFF_BLO + 64 * AST * 2)    // 54784

// ---------------- scratch (device globals) ----------------
__device__ float g_h[NN * NH];
__device__ float g_hmid[NN * NH];
__device__ float g_aggm[NN * NH];
__device__ float g_agg[NN * NREL * NH];
__device__ float g_pool[NG * NH];
__device__ float g_invw[NN * NREL];
__device__ int   g_cnt[NN * NREL];
__device__ int   g_off4[NN * NREL];   // per-(node,rel) CSR segment start
__device__ int   g_cur4[NN * NREL];
__device__ int   g_indeg[NN];
__device__ int   g_off[NN];
__device__ int   g_csr[NE];           // plain src, grouped by (target, rel)
__device__ int   g_rel[NE];
__device__ int   g_deg[NN];
__device__ int   g_bcnt[MAXDEG + 1];
__device__ int   g_boff[MAXDEG + 1];
__device__ int   g_bcur[MAXDEG + 1];
__device__ int   g_bnodes[NN];
__device__ int   g_total;

// ---------------- mma.sync helper ----------------
static __device__ __forceinline__ void mma16816(float* c, const uint32_t* a, const uint32_t* b) {
    asm volatile(
        "mma.sync.aligned.m16n8k16.row.col.f32.bf16.bf16.f32 "
        "{%0,%1,%2,%3}, {%4,%5,%6,%7}, {%8,%9}, {%0,%1,%2,%3};\n"
        : "+f"(c[0]), "+f"(c[1]), "+f"(c[2]), "+f"(c[3])
        : "r"(a[0]), "r"(a[1]), "r"(a[2]), "r"(a[3]), "r"(b[0]), "r"(b[1]));
}
static __device__ __forceinline__ uint32_t lds_u32(const __nv_bfloat16* p) {
    return *reinterpret_cast<const uint32_t*>(p);
}

// split one float4 (row segment of 4 k-values) into bf16 hi/lo into padded tiles
static __device__ __forceinline__ void split_store4(__nv_bfloat16* Ah, __nv_bfloat16* Al,
                                                    int row, int k, float4 v) {
    __nv_bfloat16 hx = __float2bfloat16_rn(v.x);
    __nv_bfloat16 hy = __float2bfloat16_rn(v.y);
    __nv_bfloat16 hz = __float2bfloat16_rn(v.z);
    __nv_bfloat16 hw = __float2bfloat16_rn(v.w);
    __nv_bfloat16 lx = __float2bfloat16_rn(v.x - __bfloat162float(hx));
    __nv_bfloat16 ly = __float2bfloat16_rn(v.y - __bfloat162float(hy));
    __nv_bfloat16 lz = __float2bfloat16_rn(v.z - __bfloat162float(hz));
    __nv_bfloat16 lw = __float2bfloat16_rn(v.w - __bfloat162float(hw));
    __nv_bfloat162* ph = reinterpret_cast<__nv_bfloat162*>(Ah + row * AST + k);
    __nv_bfloat162* pl = reinterpret_cast<__nv_bfloat162*>(Al + row * AST + k);
    ph[0] = __nv_bfloat162(hx, hy); ph[1] = __nv_bfloat162(hz, hw);
    pl[0] = __nv_bfloat162(lx, ly); pl[1] = __nv_bfloat162(lz, lw);
}

// transpose-load 64x64 fp32 weight chunk [k][n] -> [n][k] bf16 hi/lo padded tiles
static __device__ __forceinline__ void load_b_chunk(__nv_bfloat16* Bh, __nv_bfloat16* Bl,
                                                    const float* __restrict__ bsrc, int tid) {
#pragma unroll
    for (int i = 0; i < 32; i++) {
        int idx = i * 128 + tid;
        int k = idx >> 6, n = idx & 63;
        float val = __ldg(&bsrc[k * 64 + n]);
        __nv_bfloat16 hb = __float2bfloat16_rn(val);
        __nv_bfloat16 lb = __float2bfloat16_rn(val - __bfloat162float(hb));
        Bh[n * AST + k] = hb;
        Bl[n * AST + k] = lb;
    }
}

// warp-level 32x64 mma over one K=64 chunk; acc[2][8][4]
static __device__ __forceinline__ void mma_chunk(float acc[2][8][4],
                                                 const __nv_bfloat16* Ah, const __nv_bfloat16* Al,
                                                 const __nv_bfloat16* Bh, const __nv_bfloat16* Bl,
                                                 int wid, int lane) {
    int g = lane >> 2, t = lane & 3;
#pragma unroll
    for (int ks = 0; ks < 4; ks++) {
        int kb = ks * 16 + 2 * t;
        uint32_t ah[2][4], al[2][4];
#pragma unroll
        for (int mt = 0; mt < 2; mt++) {
            const __nv_bfloat16* ph = Ah + (wid * 32 + mt * 16 + g) * AST + kb;
            const __nv_bfloat16* pl = Al + (wid * 32 + mt * 16 + g) * AST + kb;
            ah[mt][0] = lds_u32(ph);            ah[mt][1] = lds_u32(ph + 8 * AST);
            ah[mt][2] = lds_u32(ph + 8);        ah[mt][3] = lds_u32(ph + 8 * AST + 8);
            al[mt][0] = lds_u32(pl);            al[mt][1] = lds_u32(pl + 8 * AST);
            al[mt][2] = lds_u32(pl + 8);        al[mt][3] = lds_u32(pl + 8 * AST + 8);
        }
#pragma unroll
        for (int nt = 0; nt < 8; nt++) {
            const __nv_bfloat16* qh = Bh + (nt * 8 + g) * AST + kb;
            const __nv_bfloat16* ql = Bl + (nt * 8 + g) * AST + kb;
            uint32_t bh[2] = {lds_u32(qh), lds_u32(qh + 8)};
            uint32_t bl[2] = {lds_u32(ql), lds_u32(ql + 8)};
#pragma unroll
            for (int mt = 0; mt < 2; mt++) {
                mma16816(acc[mt][nt], ah[mt], bh);
                mma16816(acc[mt][nt], ah[mt], bl);
                mma16816(acc[mt][nt], al[mt], bh);
            }
        }
    }
}

// ---------------- zero scratch ----------------
__global__ void zero_kernel() {
    int i = blockIdx.x * 256 + threadIdx.x;
    if (i < NN * NREL) { g_cnt[i] = 0; g_cur4[i] = 0; }
    if (i < NG * NH) g_pool[i] = 0.f;
    if (i <= MAXDEG) { g_bcnt[i] = 0; g_bcur[i] = 0; }
    if (i == 0) g_total = 0;
}

// ---------------- node init ----------------
__global__ void node_init_kernel(const float* __restrict__ x, const float* __restrict__ emb) {
    int n = blockIdx.x * 128 + threadIdx.x;
    if (n >= NN) return;
    const float4* xr = (const float4*)(x + (size_t)n * NFEAT);
    float best = -1e30f; int bi = 0;
#pragma unroll
    for (int q = 0; q < NFEAT / 4; q++) {
        float4 v = xr[q];
        if (v.x > best) { best = v.x; bi = q * 4 + 0; }
        if (v.y > best) { best = v.y; bi = q * 4 + 1; }
        if (v.z > best) { best = v.z; bi = q * 4 + 2; }
        if (v.w > best) { best = v.w; bi = q * 4 + 3; }
    }
    const float4* er = (const float4*)(emb + bi * NH);
    float4* hr = (float4*)(g_h + (size_t)n * NH);
#pragma unroll
    for (int q = 0; q < NH / 4; q++) hr[q] = er[q];
}

// ---------------- edge prep ----------------
__global__ void edge_prep_kernel(const float* __restrict__ ea, const int* __restrict__ ei) {
    int e = blockIdx.x * 256 + threadIdx.x;
    if (e >= NE) return;
    float4 a = ((const float4*)ea)[e];
    int rel = 0; float best = a.x;
    if (a.y > best) { best = a.y; rel = 1; }
    if (a.z > best) { best = a.z; rel = 2; }
    if (a.w > best) { best = a.w; rel = 3; }
    g_rel[e] = rel;
    atomicAdd(&g_cnt[ei[NE + e] * NREL + rel], 1);
}

// ---------------- node meta ----------------
__global__ void node_meta_kernel() {
    int n = blockIdx.x * 256 + threadIdx.x;
    int lane = threadIdx.x & 31;
    bool valid = n < NN;
    int c0 = 0, c1 = 0, c2 = 0, c3 = 0;
    if (valid) {
        c0 = g_cnt[n * NREL + 0]; c1 = g_cnt[n * NREL + 1];
        c2 = g_cnt[n * NREL + 2]; c3 = g_cnt[n * NREL + 3];
    }
    int ind = c0 + c1 + c2 + c3;
    if (valid) {
        g_invw[n * NREL + 0] = c0 ? 1.0f / (float)c0 : 0.f;
        g_invw[n * NREL + 1] = c1 ? 1.0f / (float)c1 : 0.f;
        g_invw[n * NREL + 2] = c2 ? 1.0f / (float)c2 : 0.f;
        g_invw[n * NREL + 3] = c3 ? 1.0f / (float)c3 : 0.f;
        g_indeg[n] = ind;
    }
    int incl = ind;
#pragma unroll
    for (int o = 1; o < 32; o <<= 1) {
        int t = __shfl_up_sync(0xffffffffu, incl, o);
        if (lane >= o) incl += t;
    }
    int wsum = __shfl_sync(0xffffffffu, incl, 31);
    int base = 0;
    if (lane == 0) base = atomicAdd(&g_total, wsum);
    base = __shfl_sync(0xffffffffu, base, 0);
    if (valid) {
        int off = base + incl - ind;
        g_off[n] = off;
        g_off4[n * NREL + 0] = off;
        g_off4[n * NREL + 1] = off + c0;
        g_off4[n * NREL + 2] = off + c0 + c1;
        g_off4[n * NREL + 3] = off + c0 + c1 + c2;
    }
    int d = min(ind, MAXDEG);
    if (valid) g_deg[n] = d;
    unsigned vm = __ballot_sync(0xffffffffu, valid);
    unsigned m = __match_any_sync(0xffffffffu, d) & vm;
    if (valid) {
        int leader = __ffs(m) - 1;
        if (lane == leader) atomicAdd(&g_bcnt[d], __popc(m));
    }
}

__global__ void bucket_scan_kernel() {
    if (threadIdx.x == 0) {
        int run = 0;
        for (int d = 0; d <= MAXDEG; d++) { g_boff[d] = run; run += g_bcnt[d]; }
    }
}

__global__ void csr_fill_kernel(const int* __restrict__ ei) {
    int e = blockIdx.x * 256 + threadIdx.x;
    if (e >= NE) return;
    int t = ei[NE + e];
    int slot = t * NREL + g_rel[e];
    int pos = g_off4[slot] + atomicAdd(&g_cur4[slot], 1);
    g_csr[pos] = ei[e];
}

__global__ void bucket_fill_kernel() {
    int n = blockIdx.x * 256 + threadIdx.x;
    int lane = threadIdx.x & 31;
    bool valid = n < NN;
    int d = valid ? g_deg[n] : 0;
    unsigned vm = __ballot_sync(0xffffffffu, valid);
    unsigned m = __match_any_sync(0xffffffffu, d) & vm;
    if (!valid) return;
    int leader = __ffs(m) - 1;
    int rank = __popc(m & ((1u << lane) - 1));
    int base = 0;
    if (lane == leader) base = atomicAdd(&g_bcur[d], __popc(m));
    base = __shfl_sync(0xffffffffu, base, leader);
    g_bnodes[g_boff[d] + base + rank] = n;
}

// ---------------- RGCN gather (rel-sorted segments) ----------------
__global__ __launch_bounds__(256) void rgcn_gather_kernel() {
    int tid = threadIdx.x;
    int node = blockIdx.x * 4 + (tid >> 6);
    if (node >= NN) return;
    int dim = tid & 63;
    const int* off4 = g_off4 + node * NREL;
    const int* cnt4 = g_cnt + node * NREL;
    const float* iw = g_invw + node * NREL;
    float* o = g_agg + ((size_t)node * NREL) * NH + dim;
#pragma unroll
    for (int r = 0; r < NREL; r++) {
        int beg = off4[r];
        int end = beg + cnt4[r];
        float a = 0.f;
        int i = beg;
        for (; i + 4 <= end; i += 4) {
            int s0 = __ldg(&g_csr[i]),     s1 = __ldg(&g_csr[i + 1]);
            int s2 = __ldg(&g_csr[i + 2]), s3 = __ldg(&g_csr[i + 3]);
            a += fmaxf(g_h[s0 * NH + dim], 0.f) + fmaxf(g_h[s1 * NH + dim], 0.f)
               + fmaxf(g_h[s2 * NH + dim], 0.f) + fmaxf(g_h[s3 * NH + dim], 0.f);
        }
        for (; i < end; i++)
            a += fmaxf(g_h[__ldg(&g_csr[i]) * NH + dim], 0.f);
        o[r * NH] = a * iw[r];
    }
}

// ---------------- RGCN GEMM via mma.sync bf16-split (5 K-chunks of 64) ----------------
__global__ __launch_bounds__(128) void rgcn_gemm_tc(const float* __restrict__ W,
                                                    const float* __restrict__ Wroot,
                                                    const float* __restrict__ bias) {
    extern __shared__ __align__(16) char smem[];
    __nv_bfloat16* Ah = (__nv_bfloat16*)(smem + OFF_AHI);
    __nv_bfloat16* Al = (__nv_bfloat16*)(smem + OFF_ALO);
    __nv_bfloat16* Bh = (__nv_bfloat16*)(smem + OFF_BHI);
    __nv_bfloat16* Bl = (__nv_bfloat16*)(smem + OFF_BLO);
    int tid = threadIdx.x, wid = tid >> 5, lane = tid & 31;
    int row = blockIdx.x * 128 + tid;

    float acc[2][8][4];
#pragma unroll
    for (int a = 0; a < 2; a++)
#pragma unroll
        for (int b = 0; b < 8; b++)
#pragma unroll
            for (int c = 0; c < 4; c++) acc[a][b][c] = 0.f;

    for (int c = 0; c < 5; c++) {
        if (c) __syncthreads();
        if (row < NN) {
            const float4* src = (c < 4)
                ? (const float4*)(g_agg + ((size_t)row * NREL + c) * NH)
                : (const float4*)(g_h + (size_t)row * NH);
            bool rl = (c == 4);
#pragma unroll
            for (int q = 0; q < 16; q++) {
                float4 v = src[q];
                if (rl) { v.x = fmaxf(v.x, 0.f); v.y = fmaxf(v.y, 0.f);
                          v.z = fmaxf(v.z, 0.f); v.w = fmaxf(v.w, 0.f); }
                split_store4(Ah, Al, tid, q * 4, v);
            }
        } else {
#pragma unroll
            for (int q = 0; q < 16; q++)
                split_store4(Ah, Al, tid, q * 4, make_float4(0.f, 0.f, 0.f, 0.f));
        }
        load_b_chunk(Bh, Bl, (c < 4) ? (W + c * NH * NH) : Wroot, tid);
        __syncthreads();
        mma_chunk(acc, Ah, Al, Bh, Bl, wid, lane);
    }

    int g = lane >> 2, t = lane & 3;
#pragma unroll
    for (int mt = 0; mt < 2; mt++) {
        int r0 = blockIdx.x * 128 + wid * 32 + mt * 16 + g;
        int r1 = r0 + 8;
#pragma unroll
        for (int nt = 0; nt < 8; nt++) {
            int col = nt * 8 + 2 * t;
            float b0 = __ldg(&bias[col]), b1 = __ldg(&bias[col + 1]);
            if (r0 < NN)
                *(float2*)(g_hmid + (size_t)r0 * NH + col) =
                    make_float2(acc[mt][nt][0] + b0, acc[mt][nt][1] + b1);
            if (r1 < NN)
                *(float2*)(g_hmid + (size_t)r1 * NH + col) =
                    make_float2(acc[mt][nt][2] + b0, acc[mt][nt][3] + b1);
        }
    }
}

// ---------------- MFConv gather ----------------
__global__ __launch_bounds__(256) void mf_gather_kernel() {
    int tid = threadIdx.x;
    int node = blockIdx.x * 4 + (tid >> 6);
    if (node >= NN) return;
    int dim = tid & 63;
    int beg = g_off[node];
    int end = beg + g_indeg[node];
    float acc = 0.f;
    int i = beg;
    for (; i + 4 <= end; i += 4) {
        int s0 = __ldg(&g_csr[i]),     s1 = __ldg(&g_csr[i + 1]);
        int s2 = __ldg(&g_csr[i + 2]), s3 = __ldg(&g_csr[i + 3]);
        acc += fmaxf(g_hmid[s0 * NH + dim], 0.f) + fmaxf(g_hmid[s1 * NH + dim], 0.f)
             + fmaxf(g_hmid[s2 * NH + dim], 0.f) + fmaxf(g_hmid[s3 * NH + dim], 0.f);
    }
    for (; i < end; i++)
        acc += fmaxf(g_hmid[__ldg(&g_csr[i]) * NH + dim], 0.f);
    g_aggm[node * NH + dim] = acc;
}

// ---------------- MFConv GEMM via mma.sync (bucketed, 2 K-chunks of 64) ----------------
__global__ __launch_bounds__(128) void mf_gemm_tc(const float* __restrict__ Wl,
                                                  const float* __restrict__ blv,
                                                  const float* __restrict__ Wr) {
    int d = blockIdx.y;
    int cnt = g_bcnt[d];
    int t0 = blockIdx.x * 128;
    if (t0 >= cnt) return;

    extern __shared__ __align__(16) char smem[];
    int* nodes = (int*)(smem + OFF_NODES);
    __nv_bfloat16* Ah = (__nv_bfloat16*)(smem + OFF_AHI);
    __nv_bfloat16* Al = (__nv_bfloat16*)(smem + OFF_ALO);
    __nv_bfloat16* Bh = (__nv_bfloat16*)(smem + OFF_BHI);
    __nv_bfloat16* Bl = (__nv_bfloat16*)(smem + OFF_BLO);
    int tid = threadIdx.x, wid = tid >> 5, lane = tid & 31;
    {
        int idx = t0 + tid;
        nodes[tid] = (idx < cnt) ? g_bnodes[g_boff[d] + idx] : -1;
    }
    __syncthreads();
    int mynode = nodes[tid];

    float acc[2][8][4];
#pragma unroll
    for (int a = 0; a < 2; a++)
#pragma unroll
        for (int b = 0; b < 8; b++)
#pragma unroll
            for (int cc = 0; cc < 4; cc++) acc[a][b][cc] = 0.f;

    for (int c = 0; c < 2; c++) {
        if (c) __syncthreads();
        if (mynode >= 0) {
            const float4* src = c ? (const float4*)(g_hmid + (size_t)mynode * NH)
                                  : (const float4*)(g_aggm + (size_t)mynode * NH);
            bool rl = (c == 1);
#pragma unroll
            for (int q = 0; q < 16; q++) {
                float4 v = src[q];
                if (rl) { v.x = fmaxf(v.x, 0.f); v.y = fmaxf(v.y, 0.f);
                          v.z = fmaxf(v.z, 0.f); v.w = fmaxf(v.w, 0.f); }
                split_store4(Ah, Al, tid, q * 4, v);
            }
        } else {
#pragma unroll
            for (int q = 0; q < 16; q++)
                split_store4(Ah, Al, tid, q * 4, make_float4(0.f, 0.f, 0.f, 0.f));
        }
        load_b_chunk(Bh, Bl, (c ? Wr : Wl) + d * NH * NH, tid);
        __syncthreads();
        mma_chunk(acc, Ah, Al, Bh, Bl, wid, lane);
    }

    int g = lane >> 2, t = lane & 3;
    const float* bb = blv + d * NH;
#pragma unroll
    for (int mt = 0; mt < 2; mt++) {
        int i0 = wid * 32 + mt * 16 + g;
        int n0 = nodes[i0], n1 = nodes[i0 + 8];
#pragma unroll
        for (int nt = 0; nt < 8; nt++) {
            int col = nt * 8 + 2 * t;
            float b0 = __ldg(&bb[col]), b1 = __ldg(&bb[col + 1]);
            if (n0 >= 0)
                *(float2*)(g_h + (size_t)n0 * NH + col) =
                    make_float2(acc[mt][nt][0] + b0, acc[mt][nt][1] + b1);
            if (n1 >= 0)
                *(float2*)(g_h + (size_t)n1 * NH + col) =
                    make_float2(acc[mt][nt][2] + b0, acc[mt][nt][3] + b1);
        }
    }
}

// ---------------- global add pool ----------------
__global__ void pool_kernel(const int* __restrict__ batch) {
    int i = blockIdx.x * 256 + threadIdx.x;
    int grp = i >> 6;
    if (grp * 4 >= NN) return;
    int dim = i & 63;
    int n0 = grp * 4;
    int curb = batch[n0];
    float vsum = g_h[(size_t)n0 * NH + dim];
#pragma unroll
    for (int j = 1; j < 4; j++) {
        int n = n0 + j;
        if (n >= NN) break;
        int b = batch[n];
        float v = g_h[(size_t)n * NH + dim];
        if (b == curb) vsum += v;
        else { atomicAdd(&g_pool[curb * NH + dim], vsum); curb = b; vsum = v; }
    }
    atomicAdd(&g_pool[curb * NH + dim], vsum);
}

// ---------------- head MLP ----------------
__global__ __launch_bounds__(256) void mlp_kernel(const float* __restrict__ l1w, const float* __restrict__ l1b,
                                                  const float* __restrict__ l2w, const float* __restrict__ l2b,
                                                  float* __restrict__ out) {
    __shared__ float s1[NH * NH];
    __shared__ float s2[NH * NO];
    __shared__ float sg[8][NH];
    int tid = threadIdx.x, lane = tid & 31, w = tid >> 5;
#pragma unroll
    for (int i = 0; i < 16; i++) s1[i * 256 + tid] = l1w[i * 256 + tid];
#pragma unroll
    for (int i = 0; i < 4; i++) s2[i * 256 + tid] = l2w[i * 256 + tid];
    int gidx = blockIdx.x * 8 + w;
    sg[w][lane] = g_pool[gidx * NH + lane];
    sg[w][lane + 32] = g_pool[gidx * NH + lane + 32];
    __syncthreads();
    float t0 = l1b[lane], t1 = l1b[lane + 32];
#pragma unroll 8
    for (int k = 0; k < NH; k++) {
        float gv = sg[w][k];
        t0 += gv * s1[k * NH + lane];
        t1 += gv * s1[k * NH + lane + 32];
    }
    t0 = fmaxf(t0, 0.f); t1 = fmaxf(t1, 0.f);
    __syncwarp();
    sg[w][lane] = t0; sg[w][lane + 32] = t1;
    __syncwarp();
    if (lane < NO) {
        float acc = l2b[lane];
#pragma unroll 8
        for (int j = 0; j < NH; j++) acc += sg[w][j] * s2[j * NO + lane];
        out[gidx * NO + lane] = acc;
    }
}

// ---------------- launch ----------------
extern "C" void kernel_launch(void* const* d_in, const int* in_sizes, int n_in,
                              void* d_out, int out_size) {
    const float *x, *ea, *emb, *l1w, *l1b, *l2w, *l2b;
    const int *ei, *batch;
    const float *rw[2], *rro[2], *rb[2], *wl[2], *bll[2], *wr[2];

    if (in_sizes[1] == NE * NREL) {
        x = (const float*)d_in[0];  ea = (const float*)d_in[1];
        ei = (const int*)d_in[2];   batch = (const int*)d_in[3];
        emb = (const float*)d_in[4];
        l1w = (const float*)d_in[5]; l1b = (const float*)d_in[6];
        l2w = (const float*)d_in[7]; l2b = (const float*)d_in[8];
        for (int b = 0; b < 2; b++) {
            int k = 9 + 6 * b;
            rw[b]  = (const float*)d_in[k + 0];
            rro[b] = (const float*)d_in[k + 1];
            rb[b]  = (const float*)d_in[k + 2];
            wl[b]  = (const float*)d_in[k + 3];
            bll[b] = (const float*)d_in[k + 4];
            wr[b]  = (const float*)d_in[k + 5];
        }
    } else {
        x = (const float*)d_in[0];  ei = (const int*)d_in[1];
        ea = (const float*)d_in[2]; batch = (const int*)d_in[3];
        emb = (const float*)d_in[4];
        for (int b = 0; b < 2; b++) {
            int k = 5 + 6 * b;
            rw[b]  = (const float*)d_in[k + 0];
            rro[b] = (const float*)d_in[k + 1];
            rb[b]  = (const float*)d_in[k + 2];
            wl[b]  = (const float*)d_in[k + 3];
            bll[b] = (const float*)d_in[k + 4];
            wr[b]  = (const float*)d_in[k + 5];
        }
        l1w = (const float*)d_in[17]; l1b = (const float*)d_in[18];
        l2w = (const float*)d_in[19]; l2b = (const float*)d_in[20];
    }
    float* out = (float*)d_out;

    cudaFuncSetAttribute(rgcn_gemm_tc, cudaFuncAttributeMaxDynamicSharedMemorySize, SMEM_SZ);
    cudaFuncSetAttribute(mf_gemm_tc, cudaFuncAttributeMaxDynamicSharedMemorySize, SMEM_SZ);

    zero_kernel<<<(NN * NREL + 255) / 256, 256>>>();
    node_init_kernel<<<(NN + 127) / 128, 128>>>(x, emb);
    edge_prep_kernel<<<(NE + 255) / 256, 256>>>(ea, ei);
    node_meta_kernel<<<(NN + 255) / 256, 256>>>();
    bucket_scan_kernel<<<1, 32>>>();
    csr_fill_kernel<<<(NE + 255) / 256, 256>>>(ei);
    bucket_fill_kernel<<<(NN + 255) / 256, 256>>>();

    int mtiles = (NN + 127) / 128;
    for (int b = 0; b < 2; b++) {
        rgcn_gather_kernel<<<(NN + 3) / 4, 256>>>();
        rgcn_gemm_tc<<<mtiles, 128, SMEM_SZ>>>(rw[b], rro[b], rb[b]);
        mf_gather_kernel<<<(NN + 3) / 4, 256>>>();
        mf_gemm_tc<<<dim3(mtiles, MAXDEG + 1), 128, SMEM_SZ>>>(wl[b], bll[b], wr[b]);
    }

    pool_kernel<<<(NN * NH / 4 + 255) / 256, 256>>>(batch);
    mlp_kernel<<<NG / 8, 256>>>(l1w, l1b, l2w, l2b, out);
}